// round 13
// baseline (speedup 1.0000x reference)
#include <cuda_runtime.h>
#include <cuda_fp16.h>
#include <math.h>
#include <stdint.h>

#define N_NODES 100000
#define N_EDGES 1600000
#define KIN 128
#define HD1 128
#define HD2P 192   // padded 4*48 (real 4*47=188)

// ---------------- scratch (static device globals; no allocation) ----------------
__device__ int    g_counts[N_NODES + 1];
__device__ int    g_rowoff[N_NODES + 1];
__device__ int    g_bsums[128];
__device__ int    g_csr_src[N_EDGES];
__device__ __half g_feat1h[(size_t)N_NODES * HD1];
__device__ __half g_out1h [(size_t)N_NODES * HD1];
__device__ __half g_feat2h[(size_t)N_NODES * HD2P];
__device__ float  g_el[N_NODES * 4];
__device__ float  g_er[N_NODES * 4];
__device__ float  g_W2p[KIN * HD2P];
__device__ float  g_b2p[HD2P];
__device__ float  g_al2p[HD2P];
__device__ float  g_ar2p[HD2P];

// ---------------- CSR build ----------------
__global__ void zero_counts_k(int n) {
    int i = blockIdx.x * blockDim.x + threadIdx.x;
    if (i < n) g_counts[i] = 0;
}
__global__ void hist_k(const int* __restrict__ dst) {
    int e = blockIdx.x * blockDim.x + threadIdx.x;
    if (e < N_EDGES) atomicAdd(&g_counts[dst[e]], 1);
}
__global__ void scan_block_k(int n) {
    __shared__ int sh[1024];
    int i = blockIdx.x * 1024 + threadIdx.x;
    int v = (i < n) ? g_counts[i] : 0;
    sh[threadIdx.x] = v;
    __syncthreads();
    for (int off = 1; off < 1024; off <<= 1) {
        int t = (threadIdx.x >= off) ? sh[threadIdx.x - off] : 0;
        __syncthreads();
        sh[threadIdx.x] += t;
        __syncthreads();
    }
    if (i < n) g_rowoff[i] = sh[threadIdx.x] - v;  // exclusive
    if (threadIdx.x == 1023) g_bsums[blockIdx.x] = sh[1023];
}
__global__ void scan_sums_k(int nb) {
    __shared__ int sh[128];
    int t = threadIdx.x;
    int v = (t < nb) ? g_bsums[t] : 0;
    sh[t] = v;
    __syncthreads();
    for (int off = 1; off < 128; off <<= 1) {
        int u = (t >= off) ? sh[t - off] : 0;
        __syncthreads();
        sh[t] += u;
        __syncthreads();
    }
    if (t < nb) g_bsums[t] = sh[t] - v;  // exclusive
}
__global__ void scan_add_k(int n) {
    int i = blockIdx.x * 1024 + threadIdx.x;
    if (i < n) {
        int v = g_rowoff[i] + g_bsums[blockIdx.x];
        g_rowoff[i] = v;
        g_counts[i] = v;
    }
}
__global__ void scatter_k(const int* __restrict__ src, const int* __restrict__ dst) {
    int e = blockIdx.x * blockDim.x + threadIdx.x;
    if (e >= N_EDGES) return;
    int slot = atomicAdd(&g_counts[dst[e]], 1);
    g_csr_src[slot] = src[e];
}

// ---------------- pad layer-2 params into 4x48 layout ----------------
__global__ void pad2_k(const float* __restrict__ W2, const float* __restrict__ b2,
                       const float* __restrict__ al2, const float* __restrict__ ar2) {
    int i = blockIdx.x * blockDim.x + threadIdx.x;
    if (i < KIN * HD2P) {
        int k = i / HD2P, c = i % HD2P;
        int h = c / 48, dd = c % 48;
        g_W2p[i] = (dd < 47) ? W2[k * 188 + h * 47 + dd] : 0.0f;
    }
    if (i < HD2P) {
        int h = i / 48, dd = i % 48;
        g_b2p[i]  = (dd < 47) ? b2 [h * 47 + dd] : 0.0f;
        g_al2p[i] = (dd < 47) ? al2[h * 47 + dd] : 0.0f;
        g_ar2p[i] = (dd < 47) ? ar2[h * 47 + dd] : 0.0f;
    }
}

// ---------------- tensor-core GEMM (mma.sync m16n8k16 f16->f32) ----------------
#define LDA 136
#define LDB 72

__device__ __forceinline__ void ldsm_x4(uint32_t* r, uint32_t addr) {
    asm volatile("ldmatrix.sync.aligned.m8n8.x4.shared.b16 {%0,%1,%2,%3}, [%4];"
                 : "=r"(r[0]), "=r"(r[1]), "=r"(r[2]), "=r"(r[3]) : "r"(addr));
}
__device__ __forceinline__ void ldsm_x4t(uint32_t* r, uint32_t addr) {
    asm volatile("ldmatrix.sync.aligned.m8n8.x4.trans.shared.b16 {%0,%1,%2,%3}, [%4];"
                 : "=r"(r[0]), "=r"(r[1]), "=r"(r[2]), "=r"(r[3]) : "r"(addr));
}
__device__ __forceinline__ void mma16816(float* d, const uint32_t* a, uint32_t b0, uint32_t b1) {
    asm volatile("mma.sync.aligned.m16n8k16.row.col.f32.f16.f16.f32 "
                 "{%0,%1,%2,%3}, {%4,%5,%6,%7}, {%8,%9}, {%0,%1,%2,%3};"
                 : "+f"(d[0]), "+f"(d[1]), "+f"(d[2]), "+f"(d[3])
                 : "r"(a[0]), "r"(a[1]), "r"(a[2]), "r"(a[3]), "r"(b0), "r"(b1));
}

template <bool AHALF, bool IND, bool ELER, int NP>
__global__ void __launch_bounds__(256, 2) gemm_tc_k(
    const void* __restrict__ Av, const float* __restrict__ W,
    __half* __restrict__ C, const int* __restrict__ ridx,
    const float* __restrict__ al, const float* __restrict__ ar,
    int nrows, int kout)
{
    extern __shared__ __half smh[];
    __half* As = smh;                 // [128][LDA]
    __half* Bs = smh + 128 * LDA;     // NP panels, each [128][LDB]

    int t = threadIdx.x;
    int lane = t & 31;
    int w = t >> 5;
    int wm = w & 3;
    int wn = w >> 2;
    int rowb = blockIdx.x * 128;
    int colb = blockIdx.y * 64 * NP;

    if (AHALF) {
        const __half* A = (const __half*)Av;
        #pragma unroll
        for (int i = 0; i < 8; i++) {
            int flat = t + i * 256;
            int rl = flat >> 4;
            int c8 = (flat & 15) << 3;
            int rg = rowb + rl;
            uint4 v = make_uint4(0u, 0u, 0u, 0u);
            if (rg < nrows) {
                int ra = IND ? ridx[rg] : rg;
                v = *reinterpret_cast<const uint4*>(A + (size_t)ra * KIN + c8);
            }
            *reinterpret_cast<uint4*>(As + rl * LDA + c8) = v;
        }
    } else {
        const float* A = (const float*)Av;
        #pragma unroll
        for (int i = 0; i < 16; i++) {
            int flat = t + i * 256;
            int rl = flat >> 5;
            int k4 = (flat & 31) << 2;
            int rg = rowb + rl;
            float4 v = make_float4(0.f, 0.f, 0.f, 0.f);
            if (rg < nrows) {
                int ra = IND ? ridx[rg] : rg;
                v = *reinterpret_cast<const float4*>(A + (size_t)ra * KIN + k4);
            }
            __half2 h01 = __floats2half2_rn(v.x, v.y);
            __half2 h23 = __floats2half2_rn(v.z, v.w);
            uint2 pk = make_uint2(*reinterpret_cast<unsigned int*>(&h01),
                                  *reinterpret_cast<unsigned int*>(&h23));
            *reinterpret_cast<uint2*>(As + rl * LDA + k4) = pk;
        }
    }
    const int C4 = 16 * NP;
    #pragma unroll
    for (int i = 0; i < 8 * NP; i++) {
        int flat = t + i * 256;
        int k = flat / C4;
        int c4 = (flat - k * C4) * 4;
        float4 v = *reinterpret_cast<const float4*>(W + (size_t)k * kout + colb + c4);
        __half2 h01 = __floats2half2_rn(v.x, v.y);
        __half2 h23 = __floats2half2_rn(v.z, v.w);
        uint2 pk = make_uint2(*reinterpret_cast<unsigned int*>(&h01),
                              *reinterpret_cast<unsigned int*>(&h23));
        int p  = c4 >> 6;
        int cc = c4 & 63;
        *reinterpret_cast<uint2*>(Bs + p * 128 * LDB + k * LDB + cc) = pk;
    }
    __syncthreads();

    uint32_t sA = (uint32_t)__cvta_generic_to_shared(As);
    uint32_t sB = (uint32_t)__cvta_generic_to_shared(Bs);
    uint32_t aBase = sA + 2u * ((wm * 32 + (lane & 15)) * LDA + (lane >> 4) * 8);
    uint32_t bBase = sB + 2u * ((lane & 15) * LDB + wn * 32 + (lane >> 4) * 8);

    float d[NP][2][4][4];
    #pragma unroll
    for (int p = 0; p < NP; p++)
        #pragma unroll
        for (int mt = 0; mt < 2; mt++)
            #pragma unroll
            for (int nt = 0; nt < 4; nt++)
                #pragma unroll
                for (int q = 0; q < 4; q++) d[p][mt][nt][q] = 0.f;

    #pragma unroll
    for (int ks = 0; ks < 8; ks++) {
        uint32_t a0[4], a1[4];
        ldsm_x4(a0, aBase + 2u * (ks * 16));
        ldsm_x4(a1, aBase + 2u * (16 * LDA + ks * 16));
        #pragma unroll
        for (int p = 0; p < NP; p++) {
            uint32_t b0[4], b1[4];
            uint32_t pb = bBase + (uint32_t)(p * 128 * LDB * 2);
            ldsm_x4t(b0, pb + 2u * (ks * 16 * LDB));
            ldsm_x4t(b1, pb + 2u * (ks * 16 * LDB + 16));
            mma16816(d[p][0][0], a0, b0[0], b0[1]);
            mma16816(d[p][0][1], a0, b0[2], b0[3]);
            mma16816(d[p][0][2], a0, b1[0], b1[1]);
            mma16816(d[p][0][3], a0, b1[2], b1[3]);
            mma16816(d[p][1][0], a1, b0[0], b0[1]);
            mma16816(d[p][1][1], a1, b0[2], b0[3]);
            mma16816(d[p][1][2], a1, b1[0], b1[1]);
            mma16816(d[p][1][3], a1, b1[2], b1[3]);
        }
    }

    int rbase = rowb + wm * 32 + (lane >> 2);
    int cwarp = wn * 32 + ((lane & 3) << 1);
    #pragma unroll
    for (int p = 0; p < NP; p++) {
        int cbase = colb + p * 64 + cwarp;
        #pragma unroll
        for (int mt = 0; mt < 2; mt++) {
            int r0 = rbase + mt * 16;
            #pragma unroll
            for (int nt = 0; nt < 4; nt++) {
                int c0 = cbase + nt * 8;
                if (r0 < nrows) {
                    __half2 h = __floats2half2_rn(d[p][mt][nt][0], d[p][mt][nt][1]);
                    *reinterpret_cast<__half2*>(C + (size_t)r0 * kout + c0) = h;
                }
                if (r0 + 8 < nrows) {
                    __half2 h = __floats2half2_rn(d[p][mt][nt][2], d[p][mt][nt][3]);
                    *reinterpret_cast<__half2*>(C + (size_t)(r0 + 8) * kout + c0) = h;
                }
            }
        }
    }

    if (ELER) {
        int cb = (lane & 3) << 1;
        #pragma unroll
        for (int p = 0; p < NP; p++) {
            int h = blockIdx.y * 2 * NP + p * 2 + wn;
            float elp[4] = {0.f, 0.f, 0.f, 0.f};
            float erp[4] = {0.f, 0.f, 0.f, 0.f};
            #pragma unroll
            for (int nt = 0; nt < 4; nt++) {
                float a0c = al[h * 32 + cb + nt * 8 + 0];
                float a1c = al[h * 32 + cb + nt * 8 + 1];
                float r0c = ar[h * 32 + cb + nt * 8 + 0];
                float r1c = ar[h * 32 + cb + nt * 8 + 1];
                #pragma unroll
                for (int mt = 0; mt < 2; mt++) {
                    elp[mt * 2 + 0] += d[p][mt][nt][0] * a0c + d[p][mt][nt][1] * a1c;
                    elp[mt * 2 + 1] += d[p][mt][nt][2] * a0c + d[p][mt][nt][3] * a1c;
                    erp[mt * 2 + 0] += d[p][mt][nt][0] * r0c + d[p][mt][nt][1] * r1c;
                    erp[mt * 2 + 1] += d[p][mt][nt][2] * r0c + d[p][mt][nt][3] * r1c;
                }
            }
            #pragma unroll
            for (int off = 1; off <= 2; off <<= 1) {
                #pragma unroll
                for (int q = 0; q < 4; q++) {
                    elp[q] += __shfl_xor_sync(0xffffffffu, elp[q], off);
                    erp[q] += __shfl_xor_sync(0xffffffffu, erp[q], off);
                }
            }
            if ((lane & 3) == 0) {
                #pragma unroll
                for (int q = 0; q < 4; q++) {
                    int r = rbase + (q >> 1) * 16 + (q & 1) * 8;
                    if (r < nrows) {
                        g_el[(size_t)r * 4 + h] = elp[q];
                        g_er[(size_t)r * 4 + h] = erp[q];
                    }
                }
            }
        }
    }
}

// ---------------- el/er (layer 2): per-node per-head dots on padded half feats ----------------
__global__ void eler_k(const __half* __restrict__ feat,
                       const float* __restrict__ al, const float* __restrict__ ar,
                       int hd, int dpad, int dpl)
{
    int w = (blockIdx.x * blockDim.x + threadIdx.x) >> 5;
    int lane = threadIdx.x & 31;
    if (w >= N_NODES) return;
    int h = lane >> 3;
    const __half* f = feat + (size_t)w * hd + lane * dpl;
    const float* alh = al + h * dpad + (lane & 7) * dpl;
    const float* arh = ar + h * dpad + (lane & 7) * dpl;
    float accL = 0.f, accR = 0.f;
    for (int q = 0; q < dpl; q++) {
        float v = __half2float(f[q]);
        accL = fmaf(v, alh[q], accL);
        accR = fmaf(v, arh[q], accR);
    }
    #pragma unroll
    for (int off = 4; off; off >>= 1) {
        accL += __shfl_xor_sync(0xffffffffu, accL, off);
        accR += __shfl_xor_sync(0xffffffffu, accR, off);
    }
    float l0 = __shfl_sync(0xffffffffu, accL, 0);
    float l1 = __shfl_sync(0xffffffffu, accL, 8);
    float l2 = __shfl_sync(0xffffffffu, accL, 16);
    float l3 = __shfl_sync(0xffffffffu, accL, 24);
    float r0 = __shfl_sync(0xffffffffu, accR, 0);
    float r1 = __shfl_sync(0xffffffffu, accR, 8);
    float r2 = __shfl_sync(0xffffffffu, accR, 16);
    float r3 = __shfl_sync(0xffffffffu, accR, 24);
    if (lane == 0) {
        *reinterpret_cast<float4*>(g_el + (size_t)w * 4) = make_float4(l0, l1, l2, l3);
        *reinterpret_cast<float4*>(g_er + (size_t)w * 4) = make_float4(r0, r1, r2, r3);
    }
}

// ---------------- SINGLE-PASS fused attention + aggregation, layer 1 ----------------
__global__ void attn_agg1_k(const float* __restrict__ b1)
{
    int w = (blockIdx.x * blockDim.x + threadIdx.x) >> 5;
    int lane = threadIdx.x & 31;
    if (w >= N_NODES) return;
    int s0 = g_rowoff[w], e0 = g_rowoff[w + 1];
    int hd = lane >> 3;
    float er_h = g_er[(size_t)w * 4 + hd];
    const uint2* fv = reinterpret_cast<const uint2*>(g_feat1h);

    float4 acc = make_float4(0.f, 0.f, 0.f, 0.f);
    float sm = 0.f;
    int i = s0;
    for (; i + 3 < e0; i += 4) {
        int sn[4];
        #pragma unroll
        for (int u = 0; u < 4; u++) sn[u] = g_csr_src[i + u];
        float a[4];
        #pragma unroll
        for (int u = 0; u < 4; u++) {
            float e = g_el[(size_t)sn[u] * 4 + hd] + er_h;
            e = fmaxf(e, 0.2f * e);
            a[u] = __expf(e);
            sm += a[u];
        }
        #pragma unroll
        for (int u = 0; u < 4; u++) {
            uint2 uu = fv[(size_t)sn[u] * 32 + lane];
            float2 f0 = __half22float2(*reinterpret_cast<__half2*>(&uu.x));
            float2 f1 = __half22float2(*reinterpret_cast<__half2*>(&uu.y));
            acc.x = fmaf(f0.x, a[u], acc.x); acc.y = fmaf(f0.y, a[u], acc.y);
            acc.z = fmaf(f1.x, a[u], acc.z); acc.w = fmaf(f1.y, a[u], acc.w);
        }
    }
    for (; i < e0; i++) {
        int s1 = g_csr_src[i];
        float e1 = g_el[(size_t)s1 * 4 + hd] + er_h;
        e1 = fmaxf(e1, 0.2f * e1);
        float a1 = __expf(e1);
        sm += a1;
        uint2 u1 = fv[(size_t)s1 * 32 + lane];
        float2 f10 = __half22float2(*reinterpret_cast<__half2*>(&u1.x));
        float2 f11 = __half22float2(*reinterpret_cast<__half2*>(&u1.y));
        acc.x = fmaf(f10.x, a1, acc.x); acc.y = fmaf(f10.y, a1, acc.y);
        acc.z = fmaf(f11.x, a1, acc.z); acc.w = fmaf(f11.y, a1, acc.w);
    }
    float ivh = 1.0f / fmaxf(sm, 1e-9f);
    float4 bb = *reinterpret_cast<const float4*>(b1 + lane * 4);
    acc.x = fmaf(acc.x, ivh, bb.x);
    acc.y = fmaf(acc.y, ivh, bb.y);
    acc.z = fmaf(acc.z, ivh, bb.z);
    acc.w = fmaf(acc.w, ivh, bb.w);
    acc.x = (acc.x > 0.f) ? acc.x : (__expf(acc.x) - 1.f);
    acc.y = (acc.y > 0.f) ? acc.y : (__expf(acc.y) - 1.f);
    acc.z = (acc.z > 0.f) ? acc.z : (__expf(acc.z) - 1.f);
    acc.w = (acc.w > 0.f) ? acc.w : (__expf(acc.w) - 1.f);
    __half2 h01 = __floats2half2_rn(acc.x, acc.y);
    __half2 h23 = __floats2half2_rn(acc.z, acc.w);
    uint2 pk = make_uint2(*reinterpret_cast<unsigned int*>(&h01),
                          *reinterpret_cast<unsigned int*>(&h23));
    *reinterpret_cast<uint2*>(g_out1h + (size_t)w * HD1 + lane * 4) = pk;
}

// ---------------- SINGLE-PASS fused attention + aggregation, layer 2 ----------------
__global__ void attn_agg2_k(float* __restrict__ out)
{
    __shared__ float sbuf[8][HD2P];
    int wl = threadIdx.x >> 5;
    int w = blockIdx.x * 8 + wl;
    int lane = threadIdx.x & 31;
    if (w >= N_NODES) return;
    int s0 = g_rowoff[w], e0 = g_rowoff[w + 1];
    int h = (lane < 24) ? (lane / 6) : 3;
    float er_h = g_er[(size_t)w * 4 + h];
    const uint4* fp = reinterpret_cast<const uint4*>(g_feat2h);
    bool active = (lane < 24);

    float acc[8] = {0.f, 0.f, 0.f, 0.f, 0.f, 0.f, 0.f, 0.f};
    float sm = 0.f;
    int i = s0;
    for (; i + 1 < e0; i += 2) {
        int s1 = g_csr_src[i];
        int s2 = g_csr_src[i + 1];
        float e1 = g_el[(size_t)s1 * 4 + h] + er_h;
        float e2 = g_el[(size_t)s2 * 4 + h] + er_h;
        e1 = fmaxf(e1, 0.2f * e1);
        e2 = fmaxf(e2, 0.2f * e2);
        float a1 = __expf(e1);
        float a2 = __expf(e2);
        sm += a1 + a2;
        if (active) {
            uint4 u1 = fp[(size_t)s1 * 24 + lane];
            uint4 u2 = fp[(size_t)s2 * 24 + lane];
            float2 p0 = __half22float2(*reinterpret_cast<__half2*>(&u1.x));
            float2 p1 = __half22float2(*reinterpret_cast<__half2*>(&u1.y));
            float2 p2 = __half22float2(*reinterpret_cast<__half2*>(&u1.z));
            float2 p3 = __half22float2(*reinterpret_cast<__half2*>(&u1.w));
            acc[0] = fmaf(p0.x, a1, acc[0]); acc[1] = fmaf(p0.y, a1, acc[1]);
            acc[2] = fmaf(p1.x, a1, acc[2]); acc[3] = fmaf(p1.y, a1, acc[3]);
            acc[4] = fmaf(p2.x, a1, acc[4]); acc[5] = fmaf(p2.y, a1, acc[5]);
            acc[6] = fmaf(p3.x, a1, acc[6]); acc[7] = fmaf(p3.y, a1, acc[7]);
            p0 = __half22float2(*reinterpret_cast<__half2*>(&u2.x));
            p1 = __half22float2(*reinterpret_cast<__half2*>(&u2.y));
            p2 = __half22float2(*reinterpret_cast<__half2*>(&u2.z));
            p3 = __half22float2(*reinterpret_cast<__half2*>(&u2.w));
            acc[0] = fmaf(p0.x, a2, acc[0]); acc[1] = fmaf(p0.y, a2, acc[1]);
            acc[2] = fmaf(p1.x, a2, acc[2]); acc[3] = fmaf(p1.y, a2, acc[3]);
            acc[4] = fmaf(p2.x, a2, acc[4]); acc[5] = fmaf(p2.y, a2, acc[5]);
            acc[6] = fmaf(p3.x, a2, acc[6]); acc[7] = fmaf(p3.y, a2, acc[7]);
        }
    }
    if (i < e0) {
        int s1 = g_csr_src[i];
        float e1 = g_el[(size_t)s1 * 4 + h] + er_h;
        e1 = fmaxf(e1, 0.2f * e1);
        float a1 = __expf(e1);
        sm += a1;
        if (active) {
            uint4 u1 = fp[(size_t)s1 * 24 + lane];
            float2 p0 = __half22float2(*reinterpret_cast<__half2*>(&u1.x));
            float2 p1 = __half22float2(*reinterpret_cast<__half2*>(&u1.y));
            float2 p2 = __half22float2(*reinterpret_cast<__half2*>(&u1.z));
            float2 p3 = __half22float2(*reinterpret_cast<__half2*>(&u1.w));
            acc[0] = fmaf(p0.x, a1, acc[0]); acc[1] = fmaf(p0.y, a1, acc[1]);
            acc[2] = fmaf(p1.x, a1, acc[2]); acc[3] = fmaf(p1.y, a1, acc[3]);
            acc[4] = fmaf(p2.x, a1, acc[4]); acc[5] = fmaf(p2.y, a1, acc[5]);
            acc[6] = fmaf(p3.x, a1, acc[6]); acc[7] = fmaf(p3.y, a1, acc[7]);
        }
    }
    float ivh = 1.0f / fmaxf(sm, 1e-9f);
    if (active) {
        int db = lane * 8;
        #pragma unroll
        for (int q = 0; q < 8; q++)
            sbuf[wl][db + q] = fmaf(acc[q], ivh, g_b2p[db + q]);
    }
    __syncwarp();
    for (int c = lane; c < 47; c += 32) {
        float v = sbuf[wl][c] + sbuf[wl][48 + c] + sbuf[wl][96 + c] + sbuf[wl][144 + c];
        out[(size_t)w * 47 + c] = 0.25f * v;
    }
}

// ---------------- host launcher (round-12 + diagnostic dummy attn_agg2 at slot 4) ----------------
extern "C" void kernel_launch(void* const* d_in, const int* in_sizes, int n_in,
                              void* d_out, int out_size)
{
    const float* x   = (const float*)d_in[0];
    const int*   src = (const int*)  d_in[1];
    const int*   dst = (const int*)  d_in[2];
    const int*   inv = (const int*)  d_in[3];
    const float* W1  = (const float*)d_in[4];
    const float* al1 = (const float*)d_in[5];
    const float* ar1 = (const float*)d_in[6];
    const float* b1  = (const float*)d_in[7];
    const float* W2  = (const float*)d_in[8];
    const float* al2 = (const float*)d_in[9];
    const float* ar2 = (const float*)d_in[10];
    const float* b2  = (const float*)d_in[11];
    float* out = (float*)d_out;
    (void)in_sizes; (void)n_in; (void)out_size;

    void *p_feat1 = nullptr, *p_out1 = nullptr, *p_feat2 = nullptr;
    void *p_W2p = nullptr, *p_al2p = nullptr, *p_ar2p = nullptr;
    cudaGetSymbolAddress(&p_feat1, g_feat1h);
    cudaGetSymbolAddress(&p_out1,  g_out1h);
    cudaGetSymbolAddress(&p_feat2, g_feat2h);
    cudaGetSymbolAddress(&p_W2p,   g_W2p);
    cudaGetSymbolAddress(&p_al2p,  g_al2p);
    cudaGetSymbolAddress(&p_ar2p,  g_ar2p);

    const int NP1v = N_NODES + 1;
    const int SCAN_BLOCKS = (NP1v + 1023) / 1024;
    const int EB = (N_EDGES + 255) / 256;
    const int NODE_WARP_BLOCKS = (N_NODES + 7) / 8;
    const int GB = (N_NODES + 127) / 128;

    size_t gsm1 = (size_t)(128 * LDA + 2 * 128 * LDB) * sizeof(__half);  // NP=2
    size_t gsm2 = (size_t)(128 * LDA + 1 * 128 * LDB) * sizeof(__half);  // NP=1
    cudaFuncSetAttribute((const void*)gemm_tc_k<false, false, true, 2>,
                         cudaFuncAttributeMaxDynamicSharedMemorySize, (int)gsm1);
    cudaFuncSetAttribute((const void*)gemm_tc_k<true, true, false, 1>,
                         cudaFuncAttributeMaxDynamicSharedMemorySize, (int)gsm2);

    // launches 1-3
    zero_counts_k<<<(NP1v + 255) / 256, 256>>>(NP1v);
    hist_k<<<EB, 256>>>(dst);
    pad2_k<<<(KIN * HD2P + 255) / 256, 256>>>(W2, b2, al2, ar2);

    // launch 4: DIAGNOSTIC dummy attn_agg2 for the ncu window.
    // Reads persistent device globals (zero-init on first call -> empty loops;
    // converged values on timed replays -> representative profile).
    // Its writes to `out` are overwritten by the real attn_agg2 at the end.
    attn_agg2_k<<<NODE_WARP_BLOCKS, 256>>>(out);

    // GEMM1 (NP=2) + fused eler1
    dim3 g1(GB, 1);
    gemm_tc_k<false, false, true, 2><<<g1, 256, gsm1>>>(x, W1, (__half*)p_feat1, nullptr,
                                                        al1, ar1, N_NODES, HD1);

    scan_block_k<<<SCAN_BLOCKS, 1024>>>(NP1v);
    scan_sums_k<<<1, 128>>>(SCAN_BLOCKS);
    scan_add_k<<<SCAN_BLOCKS, 1024>>>(NP1v);
    scatter_k<<<EB, 256>>>(src, dst);

    // ---- Layer 1 ----
    attn_agg1_k<<<NODE_WARP_BLOCKS, 256>>>(b1);

    // ---- Layer 2 ----
    dim3 g2(GB, 3);
    gemm_tc_k<true, true, false, 1><<<g2, 256, gsm2>>>(p_out1, (const float*)p_W2p,
                                                       (__half*)p_feat2, inv,
                                                       nullptr, nullptr, N_NODES, HD2P);
    eler_k<<<NODE_WARP_BLOCKS, 256>>>((const __half*)p_feat2,
                                      (const float*)p_al2p, (const float*)p_ar2p, HD2P, 48, 6);
    attn_agg2_k<<<NODE_WARP_BLOCKS, 256>>>(out);
}

// round 14
// speedup vs baseline: 1.3489x; 1.3489x over previous
#include <cuda_runtime.h>
#include <cuda_fp16.h>
#include <math.h>
#include <stdint.h>

#define N_NODES 100000
#define N_EDGES 1600000
#define KIN 128
#define HD1 128
#define HD2P 192   // padded 4*48 (real 4*47=188)

// ---------------- scratch (static device globals; no allocation) ----------------
__device__ int    g_counts[N_NODES + 1];
__device__ int    g_rowoff[N_NODES + 1];
__device__ int    g_bsums[128];
__device__ int    g_csr_src[N_EDGES];
__device__ __half g_feat1h[(size_t)N_NODES * HD1];
__device__ __half g_out1h [(size_t)N_NODES * HD1];
__device__ __half g_feat2h[(size_t)N_NODES * HD2P];
__device__ float  g_el[N_NODES * 4];
__device__ float  g_er[N_NODES * 4];
__device__ float  g_W2p[KIN * HD2P];
__device__ float  g_b2p[HD2P];
__device__ float  g_al2p[HD2P];
__device__ float  g_ar2p[HD2P];

// ---------------- CSR build ----------------
__global__ void zero_counts_k(int n) {
    int i = blockIdx.x * blockDim.x + threadIdx.x;
    if (i < n) g_counts[i] = 0;
}
__global__ void hist_k(const int* __restrict__ dst) {
    int e = blockIdx.x * blockDim.x + threadIdx.x;
    if (e < N_EDGES) atomicAdd(&g_counts[dst[e]], 1);
}
__global__ void scan_block_k(int n) {
    __shared__ int sh[1024];
    int i = blockIdx.x * 1024 + threadIdx.x;
    int v = (i < n) ? g_counts[i] : 0;
    sh[threadIdx.x] = v;
    __syncthreads();
    for (int off = 1; off < 1024; off <<= 1) {
        int t = (threadIdx.x >= off) ? sh[threadIdx.x - off] : 0;
        __syncthreads();
        sh[threadIdx.x] += t;
        __syncthreads();
    }
    if (i < n) g_rowoff[i] = sh[threadIdx.x] - v;  // exclusive
    if (threadIdx.x == 1023) g_bsums[blockIdx.x] = sh[1023];
}
__global__ void scan_sums_k(int nb) {
    __shared__ int sh[128];
    int t = threadIdx.x;
    int v = (t < nb) ? g_bsums[t] : 0;
    sh[t] = v;
    __syncthreads();
    for (int off = 1; off < 128; off <<= 1) {
        int u = (t >= off) ? sh[t - off] : 0;
        __syncthreads();
        sh[t] += u;
        __syncthreads();
    }
    if (t < nb) g_bsums[t] = sh[t] - v;  // exclusive
}
__global__ void scan_add_k(int n) {
    int i = blockIdx.x * 1024 + threadIdx.x;
    if (i < n) {
        int v = g_rowoff[i] + g_bsums[blockIdx.x];
        g_rowoff[i] = v;
        g_counts[i] = v;
    }
}
__global__ void scatter_k(const int* __restrict__ src, const int* __restrict__ dst) {
    int e = blockIdx.x * blockDim.x + threadIdx.x;
    if (e >= N_EDGES) return;
    int slot = atomicAdd(&g_counts[dst[e]], 1);
    g_csr_src[slot] = src[e];
}

// ---------------- pad layer-2 params into 4x48 layout ----------------
__global__ void pad2_k(const float* __restrict__ W2, const float* __restrict__ b2,
                       const float* __restrict__ al2, const float* __restrict__ ar2) {
    int i = blockIdx.x * blockDim.x + threadIdx.x;
    if (i < KIN * HD2P) {
        int k = i / HD2P, c = i % HD2P;
        int h = c / 48, dd = c % 48;
        g_W2p[i] = (dd < 47) ? W2[k * 188 + h * 47 + dd] : 0.0f;
    }
    if (i < HD2P) {
        int h = i / 48, dd = i % 48;
        g_b2p[i]  = (dd < 47) ? b2 [h * 47 + dd] : 0.0f;
        g_al2p[i] = (dd < 47) ? al2[h * 47 + dd] : 0.0f;
        g_ar2p[i] = (dd < 47) ? ar2[h * 47 + dd] : 0.0f;
    }
}

// ---------------- tensor-core GEMM (mma.sync m16n8k16 f16->f32) ----------------
#define LDA 136
#define LDB 72

__device__ __forceinline__ void ldsm_x4(uint32_t* r, uint32_t addr) {
    asm volatile("ldmatrix.sync.aligned.m8n8.x4.shared.b16 {%0,%1,%2,%3}, [%4];"
                 : "=r"(r[0]), "=r"(r[1]), "=r"(r[2]), "=r"(r[3]) : "r"(addr));
}
__device__ __forceinline__ void ldsm_x4t(uint32_t* r, uint32_t addr) {
    asm volatile("ldmatrix.sync.aligned.m8n8.x4.trans.shared.b16 {%0,%1,%2,%3}, [%4];"
                 : "=r"(r[0]), "=r"(r[1]), "=r"(r[2]), "=r"(r[3]) : "r"(addr));
}
__device__ __forceinline__ void mma16816(float* d, const uint32_t* a, uint32_t b0, uint32_t b1) {
    asm volatile("mma.sync.aligned.m16n8k16.row.col.f32.f16.f16.f32 "
                 "{%0,%1,%2,%3}, {%4,%5,%6,%7}, {%8,%9}, {%0,%1,%2,%3};"
                 : "+f"(d[0]), "+f"(d[1]), "+f"(d[2]), "+f"(d[3])
                 : "r"(a[0]), "r"(a[1]), "r"(a[2]), "r"(a[3]), "r"(b0), "r"(b1));
}

template <bool AHALF, bool IND, bool ELER, int NP>
__global__ void __launch_bounds__(256, 2) gemm_tc_k(
    const void* __restrict__ Av, const float* __restrict__ W,
    __half* __restrict__ C, const int* __restrict__ ridx,
    const float* __restrict__ al, const float* __restrict__ ar,
    int nrows, int kout)
{
    extern __shared__ __half smh[];
    __half* As = smh;                 // [128][LDA]
    __half* Bs = smh + 128 * LDA;     // NP panels, each [128][LDB]

    int t = threadIdx.x;
    int lane = t & 31;
    int w = t >> 5;
    int wm = w & 3;
    int wn = w >> 2;
    int rowb = blockIdx.x * 128;
    int colb = blockIdx.y * 64 * NP;

    if (AHALF) {
        const __half* A = (const __half*)Av;
        #pragma unroll
        for (int i = 0; i < 8; i++) {
            int flat = t + i * 256;
            int rl = flat >> 4;
            int c8 = (flat & 15) << 3;
            int rg = rowb + rl;
            uint4 v = make_uint4(0u, 0u, 0u, 0u);
            if (rg < nrows) {
                int ra = IND ? ridx[rg] : rg;
                v = *reinterpret_cast<const uint4*>(A + (size_t)ra * KIN + c8);
            }
            *reinterpret_cast<uint4*>(As + rl * LDA + c8) = v;
        }
    } else {
        const float* A = (const float*)Av;
        #pragma unroll
        for (int i = 0; i < 16; i++) {
            int flat = t + i * 256;
            int rl = flat >> 5;
            int k4 = (flat & 31) << 2;
            int rg = rowb + rl;
            float4 v = make_float4(0.f, 0.f, 0.f, 0.f);
            if (rg < nrows) {
                int ra = IND ? ridx[rg] : rg;
                v = *reinterpret_cast<const float4*>(A + (size_t)ra * KIN + k4);
            }
            __half2 h01 = __floats2half2_rn(v.x, v.y);
            __half2 h23 = __floats2half2_rn(v.z, v.w);
            uint2 pk = make_uint2(*reinterpret_cast<unsigned int*>(&h01),
                                  *reinterpret_cast<unsigned int*>(&h23));
            *reinterpret_cast<uint2*>(As + rl * LDA + k4) = pk;
        }
    }
    const int C4 = 16 * NP;
    #pragma unroll
    for (int i = 0; i < 8 * NP; i++) {
        int flat = t + i * 256;
        int k = flat / C4;
        int c4 = (flat - k * C4) * 4;
        float4 v = *reinterpret_cast<const float4*>(W + (size_t)k * kout + colb + c4);
        __half2 h01 = __floats2half2_rn(v.x, v.y);
        __half2 h23 = __floats2half2_rn(v.z, v.w);
        uint2 pk = make_uint2(*reinterpret_cast<unsigned int*>(&h01),
                              *reinterpret_cast<unsigned int*>(&h23));
        int p  = c4 >> 6;
        int cc = c4 & 63;
        *reinterpret_cast<uint2*>(Bs + p * 128 * LDB + k * LDB + cc) = pk;
    }
    __syncthreads();

    uint32_t sA = (uint32_t)__cvta_generic_to_shared(As);
    uint32_t sB = (uint32_t)__cvta_generic_to_shared(Bs);
    uint32_t aBase = sA + 2u * ((wm * 32 + (lane & 15)) * LDA + (lane >> 4) * 8);
    uint32_t bBase = sB + 2u * ((lane & 15) * LDB + wn * 32 + (lane >> 4) * 8);

    float d[NP][2][4][4];
    #pragma unroll
    for (int p = 0; p < NP; p++)
        #pragma unroll
        for (int mt = 0; mt < 2; mt++)
            #pragma unroll
            for (int nt = 0; nt < 4; nt++)
                #pragma unroll
                for (int q = 0; q < 4; q++) d[p][mt][nt][q] = 0.f;

    #pragma unroll
    for (int ks = 0; ks < 8; ks++) {
        uint32_t a0[4], a1[4];
        ldsm_x4(a0, aBase + 2u * (ks * 16));
        ldsm_x4(a1, aBase + 2u * (16 * LDA + ks * 16));
        #pragma unroll
        for (int p = 0; p < NP; p++) {
            uint32_t b0[4], b1[4];
            uint32_t pb = bBase + (uint32_t)(p * 128 * LDB * 2);
            ldsm_x4t(b0, pb + 2u * (ks * 16 * LDB));
            ldsm_x4t(b1, pb + 2u * (ks * 16 * LDB + 16));
            mma16816(d[p][0][0], a0, b0[0], b0[1]);
            mma16816(d[p][0][1], a0, b0[2], b0[3]);
            mma16816(d[p][0][2], a0, b1[0], b1[1]);
            mma16816(d[p][0][3], a0, b1[2], b1[3]);
            mma16816(d[p][1][0], a1, b0[0], b0[1]);
            mma16816(d[p][1][1], a1, b0[2], b0[3]);
            mma16816(d[p][1][2], a1, b1[0], b1[1]);
            mma16816(d[p][1][3], a1, b1[2], b1[3]);
        }
    }

    int rbase = rowb + wm * 32 + (lane >> 2);
    int cwarp = wn * 32 + ((lane & 3) << 1);
    #pragma unroll
    for (int p = 0; p < NP; p++) {
        int cbase = colb + p * 64 + cwarp;
        #pragma unroll
        for (int mt = 0; mt < 2; mt++) {
            int r0 = rbase + mt * 16;
            #pragma unroll
            for (int nt = 0; nt < 4; nt++) {
                int c0 = cbase + nt * 8;
                if (r0 < nrows) {
                    __half2 h = __floats2half2_rn(d[p][mt][nt][0], d[p][mt][nt][1]);
                    *reinterpret_cast<__half2*>(C + (size_t)r0 * kout + c0) = h;
                }
                if (r0 + 8 < nrows) {
                    __half2 h = __floats2half2_rn(d[p][mt][nt][2], d[p][mt][nt][3]);
                    *reinterpret_cast<__half2*>(C + (size_t)(r0 + 8) * kout + c0) = h;
                }
            }
        }
    }

    if (ELER) {
        int cb = (lane & 3) << 1;
        #pragma unroll
        for (int p = 0; p < NP; p++) {
            int h = blockIdx.y * 2 * NP + p * 2 + wn;
            float elp[4] = {0.f, 0.f, 0.f, 0.f};
            float erp[4] = {0.f, 0.f, 0.f, 0.f};
            #pragma unroll
            for (int nt = 0; nt < 4; nt++) {
                float a0c = al[h * 32 + cb + nt * 8 + 0];
                float a1c = al[h * 32 + cb + nt * 8 + 1];
                float r0c = ar[h * 32 + cb + nt * 8 + 0];
                float r1c = ar[h * 32 + cb + nt * 8 + 1];
                #pragma unroll
                for (int mt = 0; mt < 2; mt++) {
                    elp[mt * 2 + 0] += d[p][mt][nt][0] * a0c + d[p][mt][nt][1] * a1c;
                    elp[mt * 2 + 1] += d[p][mt][nt][2] * a0c + d[p][mt][nt][3] * a1c;
                    erp[mt * 2 + 0] += d[p][mt][nt][0] * r0c + d[p][mt][nt][1] * r1c;
                    erp[mt * 2 + 1] += d[p][mt][nt][2] * r0c + d[p][mt][nt][3] * r1c;
                }
            }
            #pragma unroll
            for (int off = 1; off <= 2; off <<= 1) {
                #pragma unroll
                for (int q = 0; q < 4; q++) {
                    elp[q] += __shfl_xor_sync(0xffffffffu, elp[q], off);
                    erp[q] += __shfl_xor_sync(0xffffffffu, erp[q], off);
                }
            }
            if ((lane & 3) == 0) {
                #pragma unroll
                for (int q = 0; q < 4; q++) {
                    int r = rbase + (q >> 1) * 16 + (q & 1) * 8;
                    if (r < nrows) {
                        g_el[(size_t)r * 4 + h] = elp[q];
                        g_er[(size_t)r * 4 + h] = erp[q];
                    }
                }
            }
        }
    }
}

// ---------------- el/er (layer 2): per-node per-head dots on padded half feats ----------------
__global__ void eler_k(const __half* __restrict__ feat,
                       const float* __restrict__ al, const float* __restrict__ ar,
                       int hd, int dpad, int dpl)
{
    int w = (blockIdx.x * blockDim.x + threadIdx.x) >> 5;
    int lane = threadIdx.x & 31;
    if (w >= N_NODES) return;
    int h = lane >> 3;
    const __half* f = feat + (size_t)w * hd + lane * dpl;
    const float* alh = al + h * dpad + (lane & 7) * dpl;
    const float* arh = ar + h * dpad + (lane & 7) * dpl;
    float accL = 0.f, accR = 0.f;
    for (int q = 0; q < dpl; q++) {
        float v = __half2float(f[q]);
        accL = fmaf(v, alh[q], accL);
        accR = fmaf(v, arh[q], accR);
    }
    #pragma unroll
    for (int off = 4; off; off >>= 1) {
        accL += __shfl_xor_sync(0xffffffffu, accL, off);
        accR += __shfl_xor_sync(0xffffffffu, accR, off);
    }
    float l0 = __shfl_sync(0xffffffffu, accL, 0);
    float l1 = __shfl_sync(0xffffffffu, accL, 8);
    float l2 = __shfl_sync(0xffffffffu, accL, 16);
    float l3 = __shfl_sync(0xffffffffu, accL, 24);
    float r0 = __shfl_sync(0xffffffffu, accR, 0);
    float r1 = __shfl_sync(0xffffffffu, accR, 8);
    float r2 = __shfl_sync(0xffffffffu, accR, 16);
    float r3 = __shfl_sync(0xffffffffu, accR, 24);
    if (lane == 0) {
        *reinterpret_cast<float4*>(g_el + (size_t)w * 4) = make_float4(l0, l1, l2, l3);
        *reinterpret_cast<float4*>(g_er + (size_t)w * 4) = make_float4(r0, r1, r2, r3);
    }
}

// ---------------- SINGLE-PASS fused attention + aggregation, layer 1 ----------------
__global__ void attn_agg1_k(const float* __restrict__ b1)
{
    int w = (blockIdx.x * blockDim.x + threadIdx.x) >> 5;
    int lane = threadIdx.x & 31;
    if (w >= N_NODES) return;
    int s0 = g_rowoff[w], e0 = g_rowoff[w + 1];
    int hd = lane >> 3;
    float er_h = g_er[(size_t)w * 4 + hd];
    const uint2* fv = reinterpret_cast<const uint2*>(g_feat1h);

    float4 acc = make_float4(0.f, 0.f, 0.f, 0.f);
    float sm = 0.f;
    int i = s0;
    for (; i + 3 < e0; i += 4) {
        int sn[4];
        #pragma unroll
        for (int u = 0; u < 4; u++) sn[u] = g_csr_src[i + u];
        float a[4];
        #pragma unroll
        for (int u = 0; u < 4; u++) {
            float e = g_el[(size_t)sn[u] * 4 + hd] + er_h;
            e = fmaxf(e, 0.2f * e);
            a[u] = __expf(e);
            sm += a[u];
        }
        #pragma unroll
        for (int u = 0; u < 4; u++) {
            uint2 uu = fv[(size_t)sn[u] * 32 + lane];
            float2 f0 = __half22float2(*reinterpret_cast<__half2*>(&uu.x));
            float2 f1 = __half22float2(*reinterpret_cast<__half2*>(&uu.y));
            acc.x = fmaf(f0.x, a[u], acc.x); acc.y = fmaf(f0.y, a[u], acc.y);
            acc.z = fmaf(f1.x, a[u], acc.z); acc.w = fmaf(f1.y, a[u], acc.w);
        }
    }
    for (; i < e0; i++) {
        int s1 = g_csr_src[i];
        float e1 = g_el[(size_t)s1 * 4 + hd] + er_h;
        e1 = fmaxf(e1, 0.2f * e1);
        float a1 = __expf(e1);
        sm += a1;
        uint2 u1 = fv[(size_t)s1 * 32 + lane];
        float2 f10 = __half22float2(*reinterpret_cast<__half2*>(&u1.x));
        float2 f11 = __half22float2(*reinterpret_cast<__half2*>(&u1.y));
        acc.x = fmaf(f10.x, a1, acc.x); acc.y = fmaf(f10.y, a1, acc.y);
        acc.z = fmaf(f11.x, a1, acc.z); acc.w = fmaf(f11.y, a1, acc.w);
    }
    float ivh = 1.0f / fmaxf(sm, 1e-9f);
    float4 bb = *reinterpret_cast<const float4*>(b1 + lane * 4);
    acc.x = fmaf(acc.x, ivh, bb.x);
    acc.y = fmaf(acc.y, ivh, bb.y);
    acc.z = fmaf(acc.z, ivh, bb.z);
    acc.w = fmaf(acc.w, ivh, bb.w);
    acc.x = (acc.x > 0.f) ? acc.x : (__expf(acc.x) - 1.f);
    acc.y = (acc.y > 0.f) ? acc.y : (__expf(acc.y) - 1.f);
    acc.z = (acc.z > 0.f) ? acc.z : (__expf(acc.z) - 1.f);
    acc.w = (acc.w > 0.f) ? acc.w : (__expf(acc.w) - 1.f);
    __half2 h01 = __floats2half2_rn(acc.x, acc.y);
    __half2 h23 = __floats2half2_rn(acc.z, acc.w);
    uint2 pk = make_uint2(*reinterpret_cast<unsigned int*>(&h01),
                          *reinterpret_cast<unsigned int*>(&h23));
    *reinterpret_cast<uint2*>(g_out1h + (size_t)w * HD1 + lane * 4) = pk;
}

// ---------------- SINGLE-PASS fused attention + aggregation, layer 2 ----------------
__global__ void attn_agg2_k(float* __restrict__ out)
{
    __shared__ float sbuf[8][HD2P];
    int wl = threadIdx.x >> 5;
    int w = blockIdx.x * 8 + wl;
    int lane = threadIdx.x & 31;
    if (w >= N_NODES) return;
    int s0 = g_rowoff[w], e0 = g_rowoff[w + 1];
    int h = (lane < 24) ? (lane / 6) : 3;
    float er_h = g_er[(size_t)w * 4 + h];
    const uint4* fp = reinterpret_cast<const uint4*>(g_feat2h);
    bool active = (lane < 24);

    float acc[8] = {0.f, 0.f, 0.f, 0.f, 0.f, 0.f, 0.f, 0.f};
    float sm = 0.f;
    int i = s0;
    for (; i + 1 < e0; i += 2) {
        int s1 = g_csr_src[i];
        int s2 = g_csr_src[i + 1];
        float e1 = g_el[(size_t)s1 * 4 + h] + er_h;
        float e2 = g_el[(size_t)s2 * 4 + h] + er_h;
        e1 = fmaxf(e1, 0.2f * e1);
        e2 = fmaxf(e2, 0.2f * e2);
        float a1 = __expf(e1);
        float a2 = __expf(e2);
        sm += a1 + a2;
        if (active) {
            uint4 u1 = fp[(size_t)s1 * 24 + lane];
            uint4 u2 = fp[(size_t)s2 * 24 + lane];
            float2 p0 = __half22float2(*reinterpret_cast<__half2*>(&u1.x));
            float2 p1 = __half22float2(*reinterpret_cast<__half2*>(&u1.y));
            float2 p2 = __half22float2(*reinterpret_cast<__half2*>(&u1.z));
            float2 p3 = __half22float2(*reinterpret_cast<__half2*>(&u1.w));
            acc[0] = fmaf(p0.x, a1, acc[0]); acc[1] = fmaf(p0.y, a1, acc[1]);
            acc[2] = fmaf(p1.x, a1, acc[2]); acc[3] = fmaf(p1.y, a1, acc[3]);
            acc[4] = fmaf(p2.x, a1, acc[4]); acc[5] = fmaf(p2.y, a1, acc[5]);
            acc[6] = fmaf(p3.x, a1, acc[6]); acc[7] = fmaf(p3.y, a1, acc[7]);
            p0 = __half22float2(*reinterpret_cast<__half2*>(&u2.x));
            p1 = __half22float2(*reinterpret_cast<__half2*>(&u2.y));
            p2 = __half22float2(*reinterpret_cast<__half2*>(&u2.z));
            p3 = __half22float2(*reinterpret_cast<__half2*>(&u2.w));
            acc[0] = fmaf(p0.x, a2, acc[0]); acc[1] = fmaf(p0.y, a2, acc[1]);
            acc[2] = fmaf(p1.x, a2, acc[2]); acc[3] = fmaf(p1.y, a2, acc[3]);
            acc[4] = fmaf(p2.x, a2, acc[4]); acc[5] = fmaf(p2.y, a2, acc[5]);
            acc[6] = fmaf(p3.x, a2, acc[6]); acc[7] = fmaf(p3.y, a2, acc[7]);
        }
    }
    if (i < e0) {
        int s1 = g_csr_src[i];
        float e1 = g_el[(size_t)s1 * 4 + h] + er_h;
        e1 = fmaxf(e1, 0.2f * e1);
        float a1 = __expf(e1);
        sm += a1;
        if (active) {
            uint4 u1 = fp[(size_t)s1 * 24 + lane];
            float2 p0 = __half22float2(*reinterpret_cast<__half2*>(&u1.x));
            float2 p1 = __half22float2(*reinterpret_cast<__half2*>(&u1.y));
            float2 p2 = __half22float2(*reinterpret_cast<__half2*>(&u1.z));
            float2 p3 = __half22float2(*reinterpret_cast<__half2*>(&u1.w));
            acc[0] = fmaf(p0.x, a1, acc[0]); acc[1] = fmaf(p0.y, a1, acc[1]);
            acc[2] = fmaf(p1.x, a1, acc[2]); acc[3] = fmaf(p1.y, a1, acc[3]);
            acc[4] = fmaf(p2.x, a1, acc[4]); acc[5] = fmaf(p2.y, a1, acc[5]);
            acc[6] = fmaf(p3.x, a1, acc[6]); acc[7] = fmaf(p3.y, a1, acc[7]);
        }
    }
    float ivh = 1.0f / fmaxf(sm, 1e-9f);
    if (active) {
        int db = lane * 8;
        #pragma unroll
        for (int q = 0; q < 8; q++)
            sbuf[wl][db + q] = fmaf(acc[q], ivh, g_b2p[db + q]);
    }
    __syncwarp();
    for (int c = lane; c < 47; c += 32) {
        float v = sbuf[wl][c] + sbuf[wl][48 + c] + sbuf[wl][96 + c] + sbuf[wl][144 + c];
        out[(size_t)w * 47 + c] = 0.25f * v;
    }
}

// ---------------- host launcher (round-12 + clean capture-fork streams) ----------------
extern "C" void kernel_launch(void* const* d_in, const int* in_sizes, int n_in,
                              void* d_out, int out_size)
{
    const float* x   = (const float*)d_in[0];
    const int*   src = (const int*)  d_in[1];
    const int*   dst = (const int*)  d_in[2];
    const int*   inv = (const int*)  d_in[3];
    const float* W1  = (const float*)d_in[4];
    const float* al1 = (const float*)d_in[5];
    const float* ar1 = (const float*)d_in[6];
    const float* b1  = (const float*)d_in[7];
    const float* W2  = (const float*)d_in[8];
    const float* al2 = (const float*)d_in[9];
    const float* ar2 = (const float*)d_in[10];
    const float* b2  = (const float*)d_in[11];
    float* out = (float*)d_out;
    (void)in_sizes; (void)n_in; (void)out_size;

    void *p_feat1 = nullptr, *p_out1 = nullptr, *p_feat2 = nullptr;
    void *p_W2p = nullptr, *p_al2p = nullptr, *p_ar2p = nullptr;
    cudaGetSymbolAddress(&p_feat1, g_feat1h);
    cudaGetSymbolAddress(&p_out1,  g_out1h);
    cudaGetSymbolAddress(&p_feat2, g_feat2h);
    cudaGetSymbolAddress(&p_W2p,   g_W2p);
    cudaGetSymbolAddress(&p_al2p,  g_al2p);
    cudaGetSymbolAddress(&p_ar2p,  g_ar2p);

    const int NP1v = N_NODES + 1;
    const int SCAN_BLOCKS = (NP1v + 1023) / 1024;
    const int EB = (N_EDGES + 255) / 256;
    const int NODE_WARP_BLOCKS = (N_NODES + 7) / 8;
    const int GB = (N_NODES + 127) / 128;

    size_t gsm1 = (size_t)(128 * LDA + 2 * 128 * LDB) * sizeof(__half);  // NP=2
    size_t gsm2 = (size_t)(128 * LDA + 1 * 128 * LDB) * sizeof(__half);  // NP=1
    cudaFuncSetAttribute((const void*)gemm_tc_k<false, false, true, 2>,
                         cudaFuncAttributeMaxDynamicSharedMemorySize, (int)gsm1);
    cudaFuncSetAttribute((const void*)gemm_tc_k<true, true, false, 1>,
                         cudaFuncAttributeMaxDynamicSharedMemorySize, (int)gsm2);

    cudaStream_t s1;
    cudaStreamCreateWithFlags(&s1, cudaStreamNonBlocking);
    cudaEvent_t evFork, evJoin;
    cudaEventCreateWithFlags(&evFork, cudaEventDisableTiming);
    cudaEventCreateWithFlags(&evJoin, cudaEventDisableTiming);

    // fork: branch B (s1) = pad2 + GEMM1(+eler1); branch A (default) = CSR chain
    cudaEventRecord(evFork, 0);
    cudaStreamWaitEvent(s1, evFork, 0);

    // branch B on s1
    pad2_k<<<(KIN * HD2P + 255) / 256, 256, 0, s1>>>(W2, b2, al2, ar2);
    dim3 g1(GB, 1);
    gemm_tc_k<false, false, true, 2><<<g1, 256, gsm1, s1>>>(x, W1, (__half*)p_feat1, nullptr,
                                                            al1, ar1, N_NODES, HD1);

    // branch A on default stream: CSR build
    zero_counts_k<<<(NP1v + 255) / 256, 256>>>(NP1v);
    hist_k<<<EB, 256>>>(dst);
    scan_block_k<<<SCAN_BLOCKS, 1024>>>(NP1v);
    scan_sums_k<<<1, 128>>>(SCAN_BLOCKS);
    scan_add_k<<<SCAN_BLOCKS, 1024>>>(NP1v);
    scatter_k<<<EB, 256>>>(src, dst);

    // join: attn_agg1 needs CSR (A) + feat1h/el/er (B)
    cudaEventRecord(evJoin, s1);
    cudaStreamWaitEvent(0, evJoin, 0);

    // ---- Layer 1 ----
    attn_agg1_k<<<NODE_WARP_BLOCKS, 256>>>(b1);

    // ---- Layer 2 ----
    dim3 g2(GB, 3);
    gemm_tc_k<true, true, false, 1><<<g2, 256, gsm2>>>(p_out1, (const float*)p_W2p,
                                                       (__half*)p_feat2, inv,
                                                       nullptr, nullptr, N_NODES, HD2P);
    eler_k<<<NODE_WARP_BLOCKS, 256>>>((const __half*)p_feat2,
                                      (const float*)p_al2p, (const float*)p_ar2p, HD2P, 48, 6);
    attn_agg2_k<<<NODE_WARP_BLOCKS, 256>>>(out);

    cudaEventDestroy(evFork);
    cudaEventDestroy(evJoin);
    cudaStreamDestroy(s1);
}

// round 15
// speedup vs baseline: 1.3534x; 1.0033x over previous
#include <cuda_runtime.h>
#include <cuda_fp16.h>
#include <math.h>
#include <stdint.h>

#define N_NODES 100000
#define N_EDGES 1600000
#define KIN 128
#define HD1 128
#define HD2P 192   // padded 4*48 (real 4*47=188)

// ---------------- scratch (static device globals; no allocation) ----------------
__device__ int    g_counts[N_NODES + 1];
__device__ int    g_rowoff[N_NODES + 1];
__device__ int    g_bsums[128];
__device__ int    g_csr_src[N_EDGES];
__device__ __half g_feat1h[(size_t)N_NODES * HD1];
__device__ __half g_out1h [(size_t)N_NODES * HD1];
__device__ __half g_feat2h[(size_t)N_NODES * HD2P];
__device__ float  g_el[N_NODES * 4];
__device__ float  g_er[N_NODES * 4];
__device__ float  g_W2p[KIN * HD2P];
__device__ float  g_b2p[HD2P];
__device__ float  g_al2p[HD2P];
__device__ float  g_ar2p[HD2P];

// ---------------- CSR build ----------------
__global__ void hist_k(const int* __restrict__ dst) {
    int e = blockIdx.x * blockDim.x + threadIdx.x;
    if (e < N_EDGES) atomicAdd(&g_counts[dst[e]], 1);
}
__global__ void scan_block_k(int n) {
    __shared__ int sh[1024];
    int i = blockIdx.x * 1024 + threadIdx.x;
    int v = (i < n) ? g_counts[i] : 0;
    sh[threadIdx.x] = v;
    __syncthreads();
    for (int off = 1; off < 1024; off <<= 1) {
        int t = (threadIdx.x >= off) ? sh[threadIdx.x - off] : 0;
        __syncthreads();
        sh[threadIdx.x] += t;
        __syncthreads();
    }
    if (i < n) g_rowoff[i] = sh[threadIdx.x] - v;  // exclusive within block
    if (threadIdx.x == 1023) g_bsums[blockIdx.x] = sh[1023];
}
// merged: each block computes its own prefix of g_bsums, adds it, seeds cursor
__global__ void scan_add_k(int n) {
    __shared__ int soff;
    if (threadIdx.x < 32) {
        int sum = 0;
        for (int j = threadIdx.x; j < blockIdx.x; j += 32) sum += g_bsums[j];
        #pragma unroll
        for (int off = 16; off; off >>= 1)
            sum += __shfl_xor_sync(0xffffffffu, sum, off);
        if (threadIdx.x == 0) soff = sum;
    }
    __syncthreads();
    int i = blockIdx.x * 1024 + threadIdx.x;
    if (i < n) {
        int v = g_rowoff[i] + soff;
        g_rowoff[i] = v;
        g_counts[i] = v;   // scatter cursor
    }
}
__global__ void scatter_k(const int* __restrict__ src, const int* __restrict__ dst) {
    int e = blockIdx.x * blockDim.x + threadIdx.x;
    if (e >= N_EDGES) return;
    int slot = atomicAdd(&g_counts[dst[e]], 1);
    g_csr_src[slot] = src[e];
}

// ---------------- pad layer-2 params into 4x48 layout ----------------
__global__ void pad2_k(const float* __restrict__ W2, const float* __restrict__ b2,
                       const float* __restrict__ al2, const float* __restrict__ ar2) {
    int i = blockIdx.x * blockDim.x + threadIdx.x;
    if (i < KIN * HD2P) {
        int k = i / HD2P, c = i % HD2P;
        int h = c / 48, dd = c % 48;
        g_W2p[i] = (dd < 47) ? W2[k * 188 + h * 47 + dd] : 0.0f;
    }
    if (i < HD2P) {
        int h = i / 48, dd = i % 48;
        g_b2p[i]  = (dd < 47) ? b2 [h * 47 + dd] : 0.0f;
        g_al2p[i] = (dd < 47) ? al2[h * 47 + dd] : 0.0f;
        g_ar2p[i] = (dd < 47) ? ar2[h * 47 + dd] : 0.0f;
    }
}

// ---------------- tensor-core GEMM (mma.sync m16n8k16 f16->f32) ----------------
#define LDA 136
#define LDB 72

__device__ __forceinline__ void ldsm_x4(uint32_t* r, uint32_t addr) {
    asm volatile("ldmatrix.sync.aligned.m8n8.x4.shared.b16 {%0,%1,%2,%3}, [%4];"
                 : "=r"(r[0]), "=r"(r[1]), "=r"(r[2]), "=r"(r[3]) : "r"(addr));
}
__device__ __forceinline__ void ldsm_x4t(uint32_t* r, uint32_t addr) {
    asm volatile("ldmatrix.sync.aligned.m8n8.x4.trans.shared.b16 {%0,%1,%2,%3}, [%4];"
                 : "=r"(r[0]), "=r"(r[1]), "=r"(r[2]), "=r"(r[3]) : "r"(addr));
}
__device__ __forceinline__ void mma16816(float* d, const uint32_t* a, uint32_t b0, uint32_t b1) {
    asm volatile("mma.sync.aligned.m16n8k16.row.col.f32.f16.f16.f32 "
                 "{%0,%1,%2,%3}, {%4,%5,%6,%7}, {%8,%9}, {%0,%1,%2,%3};"
                 : "+f"(d[0]), "+f"(d[1]), "+f"(d[2]), "+f"(d[3])
                 : "r"(a[0]), "r"(a[1]), "r"(a[2]), "r"(a[3]), "r"(b0), "r"(b1));
}

template <bool AHALF, bool IND, bool ELER, int NP>
__global__ void __launch_bounds__(256, 2) gemm_tc_k(
    const void* __restrict__ Av, const float* __restrict__ W,
    __half* __restrict__ C, const int* __restrict__ ridx,
    const float* __restrict__ al, const float* __restrict__ ar,
    int nrows, int kout)
{
    extern __shared__ __half smh[];
    __half* As = smh;                 // [128][LDA]
    __half* Bs = smh + 128 * LDA;     // NP panels, each [128][LDB]

    int t = threadIdx.x;
    int lane = t & 31;
    int w = t >> 5;
    int wm = w & 3;
    int wn = w >> 2;
    int rowb = blockIdx.x * 128;
    int colb = blockIdx.y * 64 * NP;

    if (AHALF) {
        const __half* A = (const __half*)Av;
        #pragma unroll
        for (int i = 0; i < 8; i++) {
            int flat = t + i * 256;
            int rl = flat >> 4;
            int c8 = (flat & 15) << 3;
            int rg = rowb + rl;
            uint4 v = make_uint4(0u, 0u, 0u, 0u);
            if (rg < nrows) {
                int ra = IND ? ridx[rg] : rg;
                v = *reinterpret_cast<const uint4*>(A + (size_t)ra * KIN + c8);
            }
            *reinterpret_cast<uint4*>(As + rl * LDA + c8) = v;
        }
    } else {
        const float* A = (const float*)Av;
        #pragma unroll
        for (int i = 0; i < 16; i++) {
            int flat = t + i * 256;
            int rl = flat >> 5;
            int k4 = (flat & 31) << 2;
            int rg = rowb + rl;
            float4 v = make_float4(0.f, 0.f, 0.f, 0.f);
            if (rg < nrows) {
                int ra = IND ? ridx[rg] : rg;
                v = *reinterpret_cast<const float4*>(A + (size_t)ra * KIN + k4);
            }
            __half2 h01 = __floats2half2_rn(v.x, v.y);
            __half2 h23 = __floats2half2_rn(v.z, v.w);
            uint2 pk = make_uint2(*reinterpret_cast<unsigned int*>(&h01),
                                  *reinterpret_cast<unsigned int*>(&h23));
            *reinterpret_cast<uint2*>(As + rl * LDA + k4) = pk;
        }
    }
    const int C4 = 16 * NP;
    #pragma unroll
    for (int i = 0; i < 8 * NP; i++) {
        int flat = t + i * 256;
        int k = flat / C4;
        int c4 = (flat - k * C4) * 4;
        float4 v = *reinterpret_cast<const float4*>(W + (size_t)k * kout + colb + c4);
        __half2 h01 = __floats2half2_rn(v.x, v.y);
        __half2 h23 = __floats2half2_rn(v.z, v.w);
        uint2 pk = make_uint2(*reinterpret_cast<unsigned int*>(&h01),
                              *reinterpret_cast<unsigned int*>(&h23));
        int p  = c4 >> 6;
        int cc = c4 & 63;
        *reinterpret_cast<uint2*>(Bs + p * 128 * LDB + k * LDB + cc) = pk;
    }
    __syncthreads();

    uint32_t sA = (uint32_t)__cvta_generic_to_shared(As);
    uint32_t sB = (uint32_t)__cvta_generic_to_shared(Bs);
    uint32_t aBase = sA + 2u * ((wm * 32 + (lane & 15)) * LDA + (lane >> 4) * 8);
    uint32_t bBase = sB + 2u * ((lane & 15) * LDB + wn * 32 + (lane >> 4) * 8);

    float d[NP][2][4][4];
    #pragma unroll
    for (int p = 0; p < NP; p++)
        #pragma unroll
        for (int mt = 0; mt < 2; mt++)
            #pragma unroll
            for (int nt = 0; nt < 4; nt++)
                #pragma unroll
                for (int q = 0; q < 4; q++) d[p][mt][nt][q] = 0.f;

    #pragma unroll
    for (int ks = 0; ks < 8; ks++) {
        uint32_t a0[4], a1[4];
        ldsm_x4(a0, aBase + 2u * (ks * 16));
        ldsm_x4(a1, aBase + 2u * (16 * LDA + ks * 16));
        #pragma unroll
        for (int p = 0; p < NP; p++) {
            uint32_t b0[4], b1[4];
            uint32_t pb = bBase + (uint32_t)(p * 128 * LDB * 2);
            ldsm_x4t(b0, pb + 2u * (ks * 16 * LDB));
            ldsm_x4t(b1, pb + 2u * (ks * 16 * LDB + 16));
            mma16816(d[p][0][0], a0, b0[0], b0[1]);
            mma16816(d[p][0][1], a0, b0[2], b0[3]);
            mma16816(d[p][0][2], a0, b1[0], b1[1]);
            mma16816(d[p][0][3], a0, b1[2], b1[3]);
            mma16816(d[p][1][0], a1, b0[0], b0[1]);
            mma16816(d[p][1][1], a1, b0[2], b0[3]);
            mma16816(d[p][1][2], a1, b1[0], b1[1]);
            mma16816(d[p][1][3], a1, b1[2], b1[3]);
        }
    }

    int rbase = rowb + wm * 32 + (lane >> 2);
    int cwarp = wn * 32 + ((lane & 3) << 1);
    #pragma unroll
    for (int p = 0; p < NP; p++) {
        int cbase = colb + p * 64 + cwarp;
        #pragma unroll
        for (int mt = 0; mt < 2; mt++) {
            int r0 = rbase + mt * 16;
            #pragma unroll
            for (int nt = 0; nt < 4; nt++) {
                int c0 = cbase + nt * 8;
                if (r0 < nrows) {
                    __half2 h = __floats2half2_rn(d[p][mt][nt][0], d[p][mt][nt][1]);
                    *reinterpret_cast<__half2*>(C + (size_t)r0 * kout + c0) = h;
                }
                if (r0 + 8 < nrows) {
                    __half2 h = __floats2half2_rn(d[p][mt][nt][2], d[p][mt][nt][3]);
                    *reinterpret_cast<__half2*>(C + (size_t)(r0 + 8) * kout + c0) = h;
                }
            }
        }
    }

    if (ELER) {
        int cb = (lane & 3) << 1;
        #pragma unroll
        for (int p = 0; p < NP; p++) {
            int h = blockIdx.y * 2 * NP + p * 2 + wn;
            float elp[4] = {0.f, 0.f, 0.f, 0.f};
            float erp[4] = {0.f, 0.f, 0.f, 0.f};
            #pragma unroll
            for (int nt = 0; nt < 4; nt++) {
                float a0c = al[h * 32 + cb + nt * 8 + 0];
                float a1c = al[h * 32 + cb + nt * 8 + 1];
                float r0c = ar[h * 32 + cb + nt * 8 + 0];
                float r1c = ar[h * 32 + cb + nt * 8 + 1];
                #pragma unroll
                for (int mt = 0; mt < 2; mt++) {
                    elp[mt * 2 + 0] += d[p][mt][nt][0] * a0c + d[p][mt][nt][1] * a1c;
                    elp[mt * 2 + 1] += d[p][mt][nt][2] * a0c + d[p][mt][nt][3] * a1c;
                    erp[mt * 2 + 0] += d[p][mt][nt][0] * r0c + d[p][mt][nt][1] * r1c;
                    erp[mt * 2 + 1] += d[p][mt][nt][2] * r0c + d[p][mt][nt][3] * r1c;
                }
            }
            #pragma unroll
            for (int off = 1; off <= 2; off <<= 1) {
                #pragma unroll
                for (int q = 0; q < 4; q++) {
                    elp[q] += __shfl_xor_sync(0xffffffffu, elp[q], off);
                    erp[q] += __shfl_xor_sync(0xffffffffu, erp[q], off);
                }
            }
            if ((lane & 3) == 0) {
                #pragma unroll
                for (int q = 0; q < 4; q++) {
                    int r = rbase + (q >> 1) * 16 + (q & 1) * 8;
                    if (r < nrows) {
                        g_el[(size_t)r * 4 + h] = elp[q];
                        g_er[(size_t)r * 4 + h] = erp[q];
                    }
                }
            }
        }
    }
}

// ---------------- el/er (layer 2): per-node per-head dots on padded half feats ----------------
__global__ void eler_k(const __half* __restrict__ feat,
                       const float* __restrict__ al, const float* __restrict__ ar,
                       int hd, int dpad, int dpl)
{
    int w = (blockIdx.x * blockDim.x + threadIdx.x) >> 5;
    int lane = threadIdx.x & 31;
    if (w >= N_NODES) return;
    int h = lane >> 3;
    const __half* f = feat + (size_t)w * hd + lane * dpl;
    const float* alh = al + h * dpad + (lane & 7) * dpl;
    const float* arh = ar + h * dpad + (lane & 7) * dpl;
    float accL = 0.f, accR = 0.f;
    for (int q = 0; q < dpl; q++) {
        float v = __half2float(f[q]);
        accL = fmaf(v, alh[q], accL);
        accR = fmaf(v, arh[q], accR);
    }
    #pragma unroll
    for (int off = 4; off; off >>= 1) {
        accL += __shfl_xor_sync(0xffffffffu, accL, off);
        accR += __shfl_xor_sync(0xffffffffu, accR, off);
    }
    float l0 = __shfl_sync(0xffffffffu, accL, 0);
    float l1 = __shfl_sync(0xffffffffu, accL, 8);
    float l2 = __shfl_sync(0xffffffffu, accL, 16);
    float l3 = __shfl_sync(0xffffffffu, accL, 24);
    float r0 = __shfl_sync(0xffffffffu, accR, 0);
    float r1 = __shfl_sync(0xffffffffu, accR, 8);
    float r2 = __shfl_sync(0xffffffffu, accR, 16);
    float r3 = __shfl_sync(0xffffffffu, accR, 24);
    if (lane == 0) {
        *reinterpret_cast<float4*>(g_el + (size_t)w * 4) = make_float4(l0, l1, l2, l3);
        *reinterpret_cast<float4*>(g_er + (size_t)w * 4) = make_float4(r0, r1, r2, r3);
    }
}

// ---------------- SINGLE-PASS fused attention + aggregation, layer 1 ----------------
__global__ void attn_agg1_k(const float* __restrict__ b1)
{
    int w = (blockIdx.x * blockDim.x + threadIdx.x) >> 5;
    int lane = threadIdx.x & 31;
    if (w >= N_NODES) return;
    int s0 = g_rowoff[w], e0 = g_rowoff[w + 1];
    int hd = lane >> 3;
    float er_h = g_er[(size_t)w * 4 + hd];
    const uint2* fv = reinterpret_cast<const uint2*>(g_feat1h);

    float4 acc = make_float4(0.f, 0.f, 0.f, 0.f);
    float sm = 0.f;
    int i = s0;
    for (; i + 3 < e0; i += 4) {
        int sn[4];
        #pragma unroll
        for (int u = 0; u < 4; u++) sn[u] = g_csr_src[i + u];
        float a[4];
        #pragma unroll
        for (int u = 0; u < 4; u++) {
            float e = g_el[(size_t)sn[u] * 4 + hd] + er_h;
            e = fmaxf(e, 0.2f * e);
            a[u] = __expf(e);
            sm += a[u];
        }
        #pragma unroll
        for (int u = 0; u < 4; u++) {
            uint2 uu = fv[(size_t)sn[u] * 32 + lane];
            float2 f0 = __half22float2(*reinterpret_cast<__half2*>(&uu.x));
            float2 f1 = __half22float2(*reinterpret_cast<__half2*>(&uu.y));
            acc.x = fmaf(f0.x, a[u], acc.x); acc.y = fmaf(f0.y, a[u], acc.y);
            acc.z = fmaf(f1.x, a[u], acc.z); acc.w = fmaf(f1.y, a[u], acc.w);
        }
    }
    for (; i < e0; i++) {
        int s1 = g_csr_src[i];
        float e1 = g_el[(size_t)s1 * 4 + hd] + er_h;
        e1 = fmaxf(e1, 0.2f * e1);
        float a1 = __expf(e1);
        sm += a1;
        uint2 u1 = fv[(size_t)s1 * 32 + lane];
        float2 f10 = __half22float2(*reinterpret_cast<__half2*>(&u1.x));
        float2 f11 = __half22float2(*reinterpret_cast<__half2*>(&u1.y));
        acc.x = fmaf(f10.x, a1, acc.x); acc.y = fmaf(f10.y, a1, acc.y);
        acc.z = fmaf(f11.x, a1, acc.z); acc.w = fmaf(f11.y, a1, acc.w);
    }
    float ivh = 1.0f / fmaxf(sm, 1e-9f);
    float4 bb = *reinterpret_cast<const float4*>(b1 + lane * 4);
    acc.x = fmaf(acc.x, ivh, bb.x);
    acc.y = fmaf(acc.y, ivh, bb.y);
    acc.z = fmaf(acc.z, ivh, bb.z);
    acc.w = fmaf(acc.w, ivh, bb.w);
    acc.x = (acc.x > 0.f) ? acc.x : (__expf(acc.x) - 1.f);
    acc.y = (acc.y > 0.f) ? acc.y : (__expf(acc.y) - 1.f);
    acc.z = (acc.z > 0.f) ? acc.z : (__expf(acc.z) - 1.f);
    acc.w = (acc.w > 0.f) ? acc.w : (__expf(acc.w) - 1.f);
    __half2 h01 = __floats2half2_rn(acc.x, acc.y);
    __half2 h23 = __floats2half2_rn(acc.z, acc.w);
    uint2 pk = make_uint2(*reinterpret_cast<unsigned int*>(&h01),
                          *reinterpret_cast<unsigned int*>(&h23));
    *reinterpret_cast<uint2*>(g_out1h + (size_t)w * HD1 + lane * 4) = pk;
}

// ---------------- SINGLE-PASS fused attention + aggregation, layer 2 ----------------
__global__ void attn_agg2_k(float* __restrict__ out)
{
    __shared__ float sbuf[8][HD2P];
    int wl = threadIdx.x >> 5;
    int w = blockIdx.x * 8 + wl;
    int lane = threadIdx.x & 31;
    if (w >= N_NODES) return;
    int s0 = g_rowoff[w], e0 = g_rowoff[w + 1];
    int h = (lane < 24) ? (lane / 6) : 3;
    float er_h = g_er[(size_t)w * 4 + h];
    const uint4* fp = reinterpret_cast<const uint4*>(g_feat2h);
    bool active = (lane < 24);

    float acc[8] = {0.f, 0.f, 0.f, 0.f, 0.f, 0.f, 0.f, 0.f};
    float sm = 0.f;
    int i = s0;
    for (; i + 1 < e0; i += 2) {
        int s1 = g_csr_src[i];
        int s2 = g_csr_src[i + 1];
        float e1 = g_el[(size_t)s1 * 4 + h] + er_h;
        float e2 = g_el[(size_t)s2 * 4 + h] + er_h;
        e1 = fmaxf(e1, 0.2f * e1);
        e2 = fmaxf(e2, 0.2f * e2);
        float a1 = __expf(e1);
        float a2 = __expf(e2);
        sm += a1 + a2;
        if (active) {
            uint4 u1 = fp[(size_t)s1 * 24 + lane];
            uint4 u2 = fp[(size_t)s2 * 24 + lane];
            float2 p0 = __half22float2(*reinterpret_cast<__half2*>(&u1.x));
            float2 p1 = __half22float2(*reinterpret_cast<__half2*>(&u1.y));
            float2 p2 = __half22float2(*reinterpret_cast<__half2*>(&u1.z));
            float2 p3 = __half22float2(*reinterpret_cast<__half2*>(&u1.w));
            acc[0] = fmaf(p0.x, a1, acc[0]); acc[1] = fmaf(p0.y, a1, acc[1]);
            acc[2] = fmaf(p1.x, a1, acc[2]); acc[3] = fmaf(p1.y, a1, acc[3]);
            acc[4] = fmaf(p2.x, a1, acc[4]); acc[5] = fmaf(p2.y, a1, acc[5]);
            acc[6] = fmaf(p3.x, a1, acc[6]); acc[7] = fmaf(p3.y, a1, acc[7]);
            p0 = __half22float2(*reinterpret_cast<__half2*>(&u2.x));
            p1 = __half22float2(*reinterpret_cast<__half2*>(&u2.y));
            p2 = __half22float2(*reinterpret_cast<__half2*>(&u2.z));
            p3 = __half22float2(*reinterpret_cast<__half2*>(&u2.w));
            acc[0] = fmaf(p0.x, a2, acc[0]); acc[1] = fmaf(p0.y, a2, acc[1]);
            acc[2] = fmaf(p1.x, a2, acc[2]); acc[3] = fmaf(p1.y, a2, acc[3]);
            acc[4] = fmaf(p2.x, a2, acc[4]); acc[5] = fmaf(p2.y, a2, acc[5]);
            acc[6] = fmaf(p3.x, a2, acc[6]); acc[7] = fmaf(p3.y, a2, acc[7]);
        }
    }
    if (i < e0) {
        int s1 = g_csr_src[i];
        float e1 = g_el[(size_t)s1 * 4 + h] + er_h;
        e1 = fmaxf(e1, 0.2f * e1);
        float a1 = __expf(e1);
        sm += a1;
        if (active) {
            uint4 u1 = fp[(size_t)s1 * 24 + lane];
            float2 p0 = __half22float2(*reinterpret_cast<__half2*>(&u1.x));
            float2 p1 = __half22float2(*reinterpret_cast<__half2*>(&u1.y));
            float2 p2 = __half22float2(*reinterpret_cast<__half2*>(&u1.z));
            float2 p3 = __half22float2(*reinterpret_cast<__half2*>(&u1.w));
            acc[0] = fmaf(p0.x, a1, acc[0]); acc[1] = fmaf(p0.y, a1, acc[1]);
            acc[2] = fmaf(p1.x, a1, acc[2]); acc[3] = fmaf(p1.y, a1, acc[3]);
            acc[4] = fmaf(p2.x, a1, acc[4]); acc[5] = fmaf(p2.y, a1, acc[5]);
            acc[6] = fmaf(p3.x, a1, acc[6]); acc[7] = fmaf(p3.y, a1, acc[7]);
        }
    }
    float ivh = 1.0f / fmaxf(sm, 1e-9f);
    if (active) {
        int db = lane * 8;
        #pragma unroll
        for (int q = 0; q < 8; q++)
            sbuf[wl][db + q] = fmaf(acc[q], ivh, g_b2p[db + q]);
    }
    __syncwarp();
    for (int c = lane; c < 47; c += 32) {
        float v = sbuf[wl][c] + sbuf[wl][48 + c] + sbuf[wl][96 + c] + sbuf[wl][144 + c];
        out[(size_t)w * 47 + c] = 0.25f * v;
    }
}

// ---------------- host launcher (streams + reduced launch count) ----------------
extern "C" void kernel_launch(void* const* d_in, const int* in_sizes, int n_in,
                              void* d_out, int out_size)
{
    const float* x   = (const float*)d_in[0];
    const int*   src = (const int*)  d_in[1];
    const int*   dst = (const int*)  d_in[2];
    const int*   inv = (const int*)  d_in[3];
    const float* W1  = (const float*)d_in[4];
    const float* al1 = (const float*)d_in[5];
    const float* ar1 = (const float*)d_in[6];
    const float* b1  = (const float*)d_in[7];
    const float* W2  = (const float*)d_in[8];
    const float* al2 = (const float*)d_in[9];
    const float* ar2 = (const float*)d_in[10];
    const float* b2  = (const float*)d_in[11];
    float* out = (float*)d_out;
    (void)in_sizes; (void)n_in; (void)out_size;

    void *p_feat1 = nullptr, *p_out1 = nullptr, *p_feat2 = nullptr;
    void *p_W2p = nullptr, *p_al2p = nullptr, *p_ar2p = nullptr, *p_counts = nullptr;
    cudaGetSymbolAddress(&p_feat1, g_feat1h);
    cudaGetSymbolAddress(&p_out1,  g_out1h);
    cudaGetSymbolAddress(&p_feat2, g_feat2h);
    cudaGetSymbolAddress(&p_W2p,   g_W2p);
    cudaGetSymbolAddress(&p_al2p,  g_al2p);
    cudaGetSymbolAddress(&p_ar2p,  g_ar2p);
    cudaGetSymbolAddress(&p_counts, g_counts);

    const int NP1v = N_NODES + 1;
    const int SCAN_BLOCKS = (NP1v + 1023) / 1024;
    const int EB = (N_EDGES + 255) / 256;
    const int NODE_WARP_BLOCKS = (N_NODES + 7) / 8;
    const int GB = (N_NODES + 127) / 128;

    size_t gsm1 = (size_t)(128 * LDA + 2 * 128 * LDB) * sizeof(__half);  // NP=2
    size_t gsm2 = (size_t)(128 * LDA + 1 * 128 * LDB) * sizeof(__half);  // NP=1
    cudaFuncSetAttribute((const void*)gemm_tc_k<false, false, true, 2>,
                         cudaFuncAttributeMaxDynamicSharedMemorySize, (int)gsm1);
    cudaFuncSetAttribute((const void*)gemm_tc_k<true, true, false, 1>,
                         cudaFuncAttributeMaxDynamicSharedMemorySize, (int)gsm2);

    cudaStream_t s1;
    cudaStreamCreateWithFlags(&s1, cudaStreamNonBlocking);
    cudaEvent_t evFork, evJoin;
    cudaEventCreateWithFlags(&evFork, cudaEventDisableTiming);
    cudaEventCreateWithFlags(&evJoin, cudaEventDisableTiming);

    // fork: branch B (s1) = pad2 + GEMM1(+eler1); branch A (default) = CSR chain
    cudaEventRecord(evFork, 0);
    cudaStreamWaitEvent(s1, evFork, 0);

    // branch B on s1
    pad2_k<<<(KIN * HD2P + 255) / 256, 256, 0, s1>>>(W2, b2, al2, ar2);
    dim3 g1(GB, 1);
    gemm_tc_k<false, false, true, 2><<<g1, 256, gsm1, s1>>>(x, W1, (__half*)p_feat1, nullptr,
                                                            al1, ar1, N_NODES, HD1);

    // branch A on default stream: CSR build (memset node + 4 kernels)
    cudaMemsetAsync(p_counts, 0, (size_t)NP1v * sizeof(int), 0);
    hist_k<<<EB, 256>>>(dst);
    scan_block_k<<<SCAN_BLOCKS, 1024>>>(NP1v);
    scan_add_k<<<SCAN_BLOCKS, 1024>>>(NP1v);   // merged bsums-prefix + add + cursor seed
    scatter_k<<<EB, 256>>>(src, dst);

    // join: attn_agg1 needs CSR (A) + feat1h/el/er (B)
    cudaEventRecord(evJoin, s1);
    cudaStreamWaitEvent(0, evJoin, 0);

    // ---- Layer 1 ----
    attn_agg1_k<<<NODE_WARP_BLOCKS, 256>>>(b1);

    // ---- Layer 2 ----
    dim3 g2(GB, 3);
    gemm_tc_k<true, true, false, 1><<<g2, 256, gsm2>>>(p_out1, (const float*)p_W2p,
                                                       (__half*)p_feat2, inv,
                                                       nullptr, nullptr, N_NODES, HD2P);
    eler_k<<<NODE_WARP_BLOCKS, 256>>>((const __half*)p_feat2,
                                      (const float*)p_al2p, (const float*)p_ar2p, HD2P, 48, 6);
    attn_agg2_k<<<NODE_WARP_BLOCKS, 256>>>(out);

    cudaEventDestroy(evFork);
    cudaEventDestroy(evJoin);
    cudaStreamDestroy(s1);
}

// round 16
// speedup vs baseline: 1.3655x; 1.0089x over previous
#include <cuda_runtime.h>
#include <cuda_fp16.h>
#include <math.h>
#include <stdint.h>

#define N_NODES 100000
#define N_EDGES 1600000
#define KIN 128
#define HD1 128
#define HD2P 192   // padded 4*48 (real 4*47=188)

// ---------------- scratch (static device globals; no allocation) ----------------
__device__ int    g_counts[N_NODES + 1];
__device__ int    g_rowoff[N_NODES + 1];
__device__ int    g_bsums[128];
__device__ int    g_csr_src[N_EDGES];
__device__ __half g_feat1h[(size_t)N_NODES * HD1];
__device__ __half g_out1h [(size_t)N_NODES * HD1];
__device__ __half g_feat2h[(size_t)N_NODES * HD2P];
__device__ float  g_elr[(size_t)2 * N_NODES * 4];   // [el | er]
__device__ float  g_W2p[KIN * HD2P];
__device__ float  g_b2p[HD2P];
__device__ float  g_al2p[HD2P];
__device__ float  g_ar2p[HD2P];

#define G_EL(i) g_elr[(i)]
#define G_ER(i) g_elr[(size_t)N_NODES * 4 + (i)]

// ---------------- CSR build ----------------
__global__ void hist_k(const int* __restrict__ dst) {
    int e = blockIdx.x * blockDim.x + threadIdx.x;
    if (e < N_EDGES) atomicAdd(&g_counts[dst[e]], 1);
}
__global__ void scan_block_k(int n) {
    __shared__ int sh[1024];
    int i = blockIdx.x * 1024 + threadIdx.x;
    int v = (i < n) ? g_counts[i] : 0;
    sh[threadIdx.x] = v;
    __syncthreads();
    for (int off = 1; off < 1024; off <<= 1) {
        int t = (threadIdx.x >= off) ? sh[threadIdx.x - off] : 0;
        __syncthreads();
        sh[threadIdx.x] += t;
        __syncthreads();
    }
    if (i < n) g_rowoff[i] = sh[threadIdx.x] - v;  // exclusive within block
    if (threadIdx.x == 1023) g_bsums[blockIdx.x] = sh[1023];
}
// merged: each block computes its own prefix of g_bsums, adds it, seeds cursor
__global__ void scan_add_k(int n) {
    __shared__ int soff;
    if (threadIdx.x < 32) {
        int sum = 0;
        for (int j = threadIdx.x; j < blockIdx.x; j += 32) sum += g_bsums[j];
        #pragma unroll
        for (int off = 16; off; off >>= 1)
            sum += __shfl_xor_sync(0xffffffffu, sum, off);
        if (threadIdx.x == 0) soff = sum;
    }
    __syncthreads();
    int i = blockIdx.x * 1024 + threadIdx.x;
    if (i < n) {
        int v = g_rowoff[i] + soff;
        g_rowoff[i] = v;
        g_counts[i] = v;   // scatter cursor
    }
}
__global__ void scatter_k(const int* __restrict__ src, const int* __restrict__ dst) {
    int e = blockIdx.x * blockDim.x + threadIdx.x;
    if (e >= N_EDGES) return;
    int slot = atomicAdd(&g_counts[dst[e]], 1);
    g_csr_src[slot] = src[e];
}

// ---------------- pad layer-2 params into 4x48 layout ----------------
__global__ void pad2_k(const float* __restrict__ W2, const float* __restrict__ b2,
                       const float* __restrict__ al2, const float* __restrict__ ar2) {
    int i = blockIdx.x * blockDim.x + threadIdx.x;
    if (i < KIN * HD2P) {
        int k = i / HD2P, c = i % HD2P;
        int h = c / 48, dd = c % 48;
        g_W2p[i] = (dd < 47) ? W2[k * 188 + h * 47 + dd] : 0.0f;
    }
    if (i < HD2P) {
        int h = i / 48, dd = i % 48;
        g_b2p[i]  = (dd < 47) ? b2 [h * 47 + dd] : 0.0f;
        g_al2p[i] = (dd < 47) ? al2[h * 47 + dd] : 0.0f;
        g_ar2p[i] = (dd < 47) ? ar2[h * 47 + dd] : 0.0f;
    }
}

// ---------------- tensor-core GEMM (mma.sync m16n8k16 f16->f32) ----------------
// gemm1: NP=2, grid.y=1, ELER epilogue (direct stores, 32-col slice == one head).
// gemm2: NP=1, grid.y=3, ELER2 epilogue (per-row dot vs al2p/ar2p, atomicAdd;
//        warp slice spans <=2 heads, boundary at multiples of 48).
#define LDA 136
#define LDB 72

__device__ __forceinline__ void ldsm_x4(uint32_t* r, uint32_t addr) {
    asm volatile("ldmatrix.sync.aligned.m8n8.x4.shared.b16 {%0,%1,%2,%3}, [%4];"
                 : "=r"(r[0]), "=r"(r[1]), "=r"(r[2]), "=r"(r[3]) : "r"(addr));
}
__device__ __forceinline__ void ldsm_x4t(uint32_t* r, uint32_t addr) {
    asm volatile("ldmatrix.sync.aligned.m8n8.x4.trans.shared.b16 {%0,%1,%2,%3}, [%4];"
                 : "=r"(r[0]), "=r"(r[1]), "=r"(r[2]), "=r"(r[3]) : "r"(addr));
}
__device__ __forceinline__ void mma16816(float* d, const uint32_t* a, uint32_t b0, uint32_t b1) {
    asm volatile("mma.sync.aligned.m16n8k16.row.col.f32.f16.f16.f32 "
                 "{%0,%1,%2,%3}, {%4,%5,%6,%7}, {%8,%9}, {%0,%1,%2,%3};"
                 : "+f"(d[0]), "+f"(d[1]), "+f"(d[2]), "+f"(d[3])
                 : "r"(a[0]), "r"(a[1]), "r"(a[2]), "r"(a[3]), "r"(b0), "r"(b1));
}

template <bool AHALF, bool IND, bool ELER, bool ELER2, int NP>
__global__ void __launch_bounds__(256, 2) gemm_tc_k(
    const void* __restrict__ Av, const float* __restrict__ W,
    __half* __restrict__ C, const int* __restrict__ ridx,
    const float* __restrict__ al, const float* __restrict__ ar,
    int nrows, int kout)
{
    extern __shared__ __half smh[];
    __half* As = smh;                 // [128][LDA]
    __half* Bs = smh + 128 * LDA;     // NP panels, each [128][LDB]

    int t = threadIdx.x;
    int lane = t & 31;
    int w = t >> 5;
    int wm = w & 3;
    int wn = w >> 2;
    int rowb = blockIdx.x * 128;
    int colb = blockIdx.y * 64 * NP;

    if (AHALF) {
        const __half* A = (const __half*)Av;
        #pragma unroll
        for (int i = 0; i < 8; i++) {
            int flat = t + i * 256;
            int rl = flat >> 4;
            int c8 = (flat & 15) << 3;
            int rg = rowb + rl;
            uint4 v = make_uint4(0u, 0u, 0u, 0u);
            if (rg < nrows) {
                int ra = IND ? ridx[rg] : rg;
                v = *reinterpret_cast<const uint4*>(A + (size_t)ra * KIN + c8);
            }
            *reinterpret_cast<uint4*>(As + rl * LDA + c8) = v;
        }
    } else {
        const float* A = (const float*)Av;
        #pragma unroll
        for (int i = 0; i < 16; i++) {
            int flat = t + i * 256;
            int rl = flat >> 5;
            int k4 = (flat & 31) << 2;
            int rg = rowb + rl;
            float4 v = make_float4(0.f, 0.f, 0.f, 0.f);
            if (rg < nrows) {
                int ra = IND ? ridx[rg] : rg;
                v = *reinterpret_cast<const float4*>(A + (size_t)ra * KIN + k4);
            }
            __half2 h01 = __floats2half2_rn(v.x, v.y);
            __half2 h23 = __floats2half2_rn(v.z, v.w);
            uint2 pk = make_uint2(*reinterpret_cast<unsigned int*>(&h01),
                                  *reinterpret_cast<unsigned int*>(&h23));
            *reinterpret_cast<uint2*>(As + rl * LDA + k4) = pk;
        }
    }
    const int C4 = 16 * NP;
    #pragma unroll
    for (int i = 0; i < 8 * NP; i++) {
        int flat = t + i * 256;
        int k = flat / C4;
        int c4 = (flat - k * C4) * 4;
        float4 v = *reinterpret_cast<const float4*>(W + (size_t)k * kout + colb + c4);
        __half2 h01 = __floats2half2_rn(v.x, v.y);
        __half2 h23 = __floats2half2_rn(v.z, v.w);
        uint2 pk = make_uint2(*reinterpret_cast<unsigned int*>(&h01),
                              *reinterpret_cast<unsigned int*>(&h23));
        int p  = c4 >> 6;
        int cc = c4 & 63;
        *reinterpret_cast<uint2*>(Bs + p * 128 * LDB + k * LDB + cc) = pk;
    }
    __syncthreads();

    uint32_t sA = (uint32_t)__cvta_generic_to_shared(As);
    uint32_t sB = (uint32_t)__cvta_generic_to_shared(Bs);
    uint32_t aBase = sA + 2u * ((wm * 32 + (lane & 15)) * LDA + (lane >> 4) * 8);
    uint32_t bBase = sB + 2u * ((lane & 15) * LDB + wn * 32 + (lane >> 4) * 8);

    float d[NP][2][4][4];
    #pragma unroll
    for (int p = 0; p < NP; p++)
        #pragma unroll
        for (int mt = 0; mt < 2; mt++)
            #pragma unroll
            for (int nt = 0; nt < 4; nt++)
                #pragma unroll
                for (int q = 0; q < 4; q++) d[p][mt][nt][q] = 0.f;

    #pragma unroll
    for (int ks = 0; ks < 8; ks++) {
        uint32_t a0[4], a1[4];
        ldsm_x4(a0, aBase + 2u * (ks * 16));
        ldsm_x4(a1, aBase + 2u * (16 * LDA + ks * 16));
        #pragma unroll
        for (int p = 0; p < NP; p++) {
            uint32_t b0[4], b1[4];
            uint32_t pb = bBase + (uint32_t)(p * 128 * LDB * 2);
            ldsm_x4t(b0, pb + 2u * (ks * 16 * LDB));
            ldsm_x4t(b1, pb + 2u * (ks * 16 * LDB + 16));
            mma16816(d[p][0][0], a0, b0[0], b0[1]);
            mma16816(d[p][0][1], a0, b0[2], b0[3]);
            mma16816(d[p][0][2], a0, b1[0], b1[1]);
            mma16816(d[p][0][3], a0, b1[2], b1[3]);
            mma16816(d[p][1][0], a1, b0[0], b0[1]);
            mma16816(d[p][1][1], a1, b0[2], b0[3]);
            mma16816(d[p][1][2], a1, b1[0], b1[1]);
            mma16816(d[p][1][3], a1, b1[2], b1[3]);
        }
    }

    int rbase = rowb + wm * 32 + (lane >> 2);
    int cwarp = wn * 32 + ((lane & 3) << 1);
    #pragma unroll
    for (int p = 0; p < NP; p++) {
        int cbase = colb + p * 64 + cwarp;
        #pragma unroll
        for (int mt = 0; mt < 2; mt++) {
            int r0 = rbase + mt * 16;
            #pragma unroll
            for (int nt = 0; nt < 4; nt++) {
                int c0 = cbase + nt * 8;
                if (r0 < nrows) {
                    __half2 h = __floats2half2_rn(d[p][mt][nt][0], d[p][mt][nt][1]);
                    *reinterpret_cast<__half2*>(C + (size_t)r0 * kout + c0) = h;
                }
                if (r0 + 8 < nrows) {
                    __half2 h = __floats2half2_rn(d[p][mt][nt][2], d[p][mt][nt][3]);
                    *reinterpret_cast<__half2*>(C + (size_t)(r0 + 8) * kout + c0) = h;
                }
            }
        }
    }

    if (ELER) {
        // layer 1: each warp's 32-col slice == exactly one head; direct stores
        int cb = (lane & 3) << 1;
        #pragma unroll
        for (int p = 0; p < NP; p++) {
            int h = blockIdx.y * 2 * NP + p * 2 + wn;
            float elp[4] = {0.f, 0.f, 0.f, 0.f};
            float erp[4] = {0.f, 0.f, 0.f, 0.f};
            #pragma unroll
            for (int nt = 0; nt < 4; nt++) {
                float a0c = al[h * 32 + cb + nt * 8 + 0];
                float a1c = al[h * 32 + cb + nt * 8 + 1];
                float r0c = ar[h * 32 + cb + nt * 8 + 0];
                float r1c = ar[h * 32 + cb + nt * 8 + 1];
                #pragma unroll
                for (int mt = 0; mt < 2; mt++) {
                    elp[mt * 2 + 0] += d[p][mt][nt][0] * a0c + d[p][mt][nt][1] * a1c;
                    elp[mt * 2 + 1] += d[p][mt][nt][2] * a0c + d[p][mt][nt][3] * a1c;
                    erp[mt * 2 + 0] += d[p][mt][nt][0] * r0c + d[p][mt][nt][1] * r1c;
                    erp[mt * 2 + 1] += d[p][mt][nt][2] * r0c + d[p][mt][nt][3] * r1c;
                }
            }
            #pragma unroll
            for (int off = 1; off <= 2; off <<= 1) {
                #pragma unroll
                for (int q = 0; q < 4; q++) {
                    elp[q] += __shfl_xor_sync(0xffffffffu, elp[q], off);
                    erp[q] += __shfl_xor_sync(0xffffffffu, erp[q], off);
                }
            }
            if ((lane & 3) == 0) {
                #pragma unroll
                for (int q = 0; q < 4; q++) {
                    int r = rbase + (q >> 1) * 16 + (q & 1) * 8;
                    if (r < nrows) {
                        G_EL((size_t)r * 4 + h) = elp[q];
                        G_ER((size_t)r * 4 + h) = erp[q];
                    }
                }
            }
        }
    }

    if (ELER2) {
        // layer 2: padded flat col c == h*48+dd, so weight = al[c] directly.
        // Warp slice spans <=2 heads (A: c < bnd, B: c >= bnd).
        int cbase0 = colb + wn * 32 + ((lane & 3) << 1);   // NP==1
        int slice0 = colb + wn * 32;
        int hbase = slice0 / 48;
        int bnd = (hbase + 1) * 48;
        float eA[4] = {0.f, 0.f, 0.f, 0.f}, eB[4] = {0.f, 0.f, 0.f, 0.f};
        float rA[4] = {0.f, 0.f, 0.f, 0.f}, rB[4] = {0.f, 0.f, 0.f, 0.f};
        #pragma unroll
        for (int mt = 0; mt < 2; mt++)
            #pragma unroll
            for (int nt = 0; nt < 4; nt++)
                #pragma unroll
                for (int q = 0; q < 4; q++) {
                    int c = cbase0 + nt * 8 + (q & 1);
                    float wl = al[c];
                    float wr = ar[c];
                    int v = mt * 2 + (q >> 1);
                    float val = d[0][mt][nt][q];
                    if (c < bnd) { eA[v] += val * wl; rA[v] += val * wr; }
                    else         { eB[v] += val * wl; rB[v] += val * wr; }
                }
        #pragma unroll
        for (int off = 1; off <= 2; off <<= 1) {
            #pragma unroll
            for (int v = 0; v < 4; v++) {
                eA[v] += __shfl_xor_sync(0xffffffffu, eA[v], off);
                eB[v] += __shfl_xor_sync(0xffffffffu, eB[v], off);
                rA[v] += __shfl_xor_sync(0xffffffffu, rA[v], off);
                rB[v] += __shfl_xor_sync(0xffffffffu, rB[v], off);
            }
        }
        if ((lane & 3) == 0) {
            bool hasB = (bnd < slice0 + 32);
            #pragma unroll
            for (int v = 0; v < 4; v++) {
                int r = rbase + (v >> 1) * 16 + (v & 1) * 8;
                if (r < nrows) {
                    atomicAdd(&G_EL((size_t)r * 4 + hbase), eA[v]);
                    atomicAdd(&G_ER((size_t)r * 4 + hbase), rA[v]);
                    if (hasB) {
                        atomicAdd(&G_EL((size_t)r * 4 + hbase + 1), eB[v]);
                        atomicAdd(&G_ER((size_t)r * 4 + hbase + 1), rB[v]);
                    }
                }
            }
        }
    }
}

// ---------------- SINGLE-PASS fused attention + aggregation, layer 1 ----------------
__global__ void attn_agg1_k(const float* __restrict__ b1)
{
    int w = (blockIdx.x * blockDim.x + threadIdx.x) >> 5;
    int lane = threadIdx.x & 31;
    if (w >= N_NODES) return;
    int s0 = g_rowoff[w], e0 = g_rowoff[w + 1];
    int hd = lane >> 3;
    float er_h = G_ER((size_t)w * 4 + hd);
    const uint2* fv = reinterpret_cast<const uint2*>(g_feat1h);

    float4 acc = make_float4(0.f, 0.f, 0.f, 0.f);
    float sm = 0.f;
    int i = s0;
    for (; i + 3 < e0; i += 4) {
        int sn[4];
        #pragma unroll
        for (int u = 0; u < 4; u++) sn[u] = g_csr_src[i + u];
        float a[4];
        #pragma unroll
        for (int u = 0; u < 4; u++) {
            float e = G_EL((size_t)sn[u] * 4 + hd) + er_h;
            e = fmaxf(e, 0.2f * e);
            a[u] = __expf(e);
            sm += a[u];
        }
        #pragma unroll
        for (int u = 0; u < 4; u++) {
            uint2 uu = fv[(size_t)sn[u] * 32 + lane];
            float2 f0 = __half22float2(*reinterpret_cast<__half2*>(&uu.x));
            float2 f1 = __half22float2(*reinterpret_cast<__half2*>(&uu.y));
            acc.x = fmaf(f0.x, a[u], acc.x); acc.y = fmaf(f0.y, a[u], acc.y);
            acc.z = fmaf(f1.x, a[u], acc.z); acc.w = fmaf(f1.y, a[u], acc.w);
        }
    }
    for (; i < e0; i++) {
        int s1 = g_csr_src[i];
        float e1 = G_EL((size_t)s1 * 4 + hd) + er_h;
        e1 = fmaxf(e1, 0.2f * e1);
        float a1 = __expf(e1);
        sm += a1;
        uint2 u1 = fv[(size_t)s1 * 32 + lane];
        float2 f10 = __half22float2(*reinterpret_cast<__half2*>(&u1.x));
        float2 f11 = __half22float2(*reinterpret_cast<__half2*>(&u1.y));
        acc.x = fmaf(f10.x, a1, acc.x); acc.y = fmaf(f10.y, a1, acc.y);
        acc.z = fmaf(f11.x, a1, acc.z); acc.w = fmaf(f11.y, a1, acc.w);
    }
    float ivh = 1.0f / fmaxf(sm, 1e-9f);
    float4 bb = *reinterpret_cast<const float4*>(b1 + lane * 4);
    acc.x = fmaf(acc.x, ivh, bb.x);
    acc.y = fmaf(acc.y, ivh, bb.y);
    acc.z = fmaf(acc.z, ivh, bb.z);
    acc.w = fmaf(acc.w, ivh, bb.w);
    acc.x = (acc.x > 0.f) ? acc.x : (__expf(acc.x) - 1.f);
    acc.y = (acc.y > 0.f) ? acc.y : (__expf(acc.y) - 1.f);
    acc.z = (acc.z > 0.f) ? acc.z : (__expf(acc.z) - 1.f);
    acc.w = (acc.w > 0.f) ? acc.w : (__expf(acc.w) - 1.f);
    __half2 h01 = __floats2half2_rn(acc.x, acc.y);
    __half2 h23 = __floats2half2_rn(acc.z, acc.w);
    uint2 pk = make_uint2(*reinterpret_cast<unsigned int*>(&h01),
                          *reinterpret_cast<unsigned int*>(&h23));
    *reinterpret_cast<uint2*>(g_out1h + (size_t)w * HD1 + lane * 4) = pk;
}

// ---------------- SINGLE-PASS fused attention + aggregation, layer 2 ----------------
__global__ void attn_agg2_k(float* __restrict__ out)
{
    __shared__ float sbuf[8][HD2P];
    int wl = threadIdx.x >> 5;
    int w = blockIdx.x * 8 + wl;
    int lane = threadIdx.x & 31;
    if (w >= N_NODES) return;
    int s0 = g_rowoff[w], e0 = g_rowoff[w + 1];
    int h = (lane < 24) ? (lane / 6) : 3;
    float er_h = G_ER((size_t)w * 4 + h);
    const uint4* fp = reinterpret_cast<const uint4*>(g_feat2h);
    bool active = (lane < 24);

    float acc[8] = {0.f, 0.f, 0.f, 0.f, 0.f, 0.f, 0.f, 0.f};
    float sm = 0.f;
    int i = s0;
    for (; i + 1 < e0; i += 2) {
        int s1 = g_csr_src[i];
        int s2 = g_csr_src[i + 1];
        float e1 = G_EL((size_t)s1 * 4 + h) + er_h;
        float e2 = G_EL((size_t)s2 * 4 + h) + er_h;
        e1 = fmaxf(e1, 0.2f * e1);
        e2 = fmaxf(e2, 0.2f * e2);
        float a1 = __expf(e1);
        float a2 = __expf(e2);
        sm += a1 + a2;
        if (active) {
            uint4 u1 = fp[(size_t)s1 * 24 + lane];
            uint4 u2 = fp[(size_t)s2 * 24 + lane];
            float2 p0 = __half22float2(*reinterpret_cast<__half2*>(&u1.x));
            float2 p1 = __half22float2(*reinterpret_cast<__half2*>(&u1.y));
            float2 p2 = __half22float2(*reinterpret_cast<__half2*>(&u1.z));
            float2 p3 = __half22float2(*reinterpret_cast<__half2*>(&u1.w));
            acc[0] = fmaf(p0.x, a1, acc[0]); acc[1] = fmaf(p0.y, a1, acc[1]);
            acc[2] = fmaf(p1.x, a1, acc[2]); acc[3] = fmaf(p1.y, a1, acc[3]);
            acc[4] = fmaf(p2.x, a1, acc[4]); acc[5] = fmaf(p2.y, a1, acc[5]);
            acc[6] = fmaf(p3.x, a1, acc[6]); acc[7] = fmaf(p3.y, a1, acc[7]);
            p0 = __half22float2(*reinterpret_cast<__half2*>(&u2.x));
            p1 = __half22float2(*reinterpret_cast<__half2*>(&u2.y));
            p2 = __half22float2(*reinterpret_cast<__half2*>(&u2.z));
            p3 = __half22float2(*reinterpret_cast<__half2*>(&u2.w));
            acc[0] = fmaf(p0.x, a2, acc[0]); acc[1] = fmaf(p0.y, a2, acc[1]);
            acc[2] = fmaf(p1.x, a2, acc[2]); acc[3] = fmaf(p1.y, a2, acc[3]);
            acc[4] = fmaf(p2.x, a2, acc[4]); acc[5] = fmaf(p2.y, a2, acc[5]);
            acc[6] = fmaf(p3.x, a2, acc[6]); acc[7] = fmaf(p3.y, a2, acc[7]);
        }
    }
    if (i < e0) {
        int s1 = g_csr_src[i];
        float e1 = G_EL((size_t)s1 * 4 + h) + er_h;
        e1 = fmaxf(e1, 0.2f * e1);
        float a1 = __expf(e1);
        sm += a1;
        if (active) {
            uint4 u1 = fp[(size_t)s1 * 24 + lane];
            float2 p0 = __half22float2(*reinterpret_cast<__half2*>(&u1.x));
            float2 p1 = __half22float2(*reinterpret_cast<__half2*>(&u1.y));
            float2 p2 = __half22float2(*reinterpret_cast<__half2*>(&u1.z));
            float2 p3 = __half22float2(*reinterpret_cast<__half2*>(&u1.w));
            acc[0] = fmaf(p0.x, a1, acc[0]); acc[1] = fmaf(p0.y, a1, acc[1]);
            acc[2] = fmaf(p1.x, a1, acc[2]); acc[3] = fmaf(p1.y, a1, acc[3]);
            acc[4] = fmaf(p2.x, a1, acc[4]); acc[5] = fmaf(p2.y, a1, acc[5]);
            acc[6] = fmaf(p3.x, a1, acc[6]); acc[7] = fmaf(p3.y, a1, acc[7]);
        }
    }
    float ivh = 1.0f / fmaxf(sm, 1e-9f);
    if (active) {
        int db = lane * 8;
        #pragma unroll
        for (int q = 0; q < 8; q++)
            sbuf[wl][db + q] = fmaf(acc[q], ivh, g_b2p[db + q]);
    }
    __syncwarp();
    for (int c = lane; c < 47; c += 32) {
        float v = sbuf[wl][c] + sbuf[wl][48 + c] + sbuf[wl][96 + c] + sbuf[wl][144 + c];
        out[(size_t)w * 47 + c] = 0.25f * v;
    }
}

// ---------------- host launcher ----------------
extern "C" void kernel_launch(void* const* d_in, const int* in_sizes, int n_in,
                              void* d_out, int out_size)
{
    const float* x   = (const float*)d_in[0];
    const int*   src = (const int*)  d_in[1];
    const int*   dst = (const int*)  d_in[2];
    const int*   inv = (const int*)  d_in[3];
    const float* W1  = (const float*)d_in[4];
    const float* al1 = (const float*)d_in[5];
    const float* ar1 = (const float*)d_in[6];
    const float* b1  = (const float*)d_in[7];
    const float* W2  = (const float*)d_in[8];
    const float* al2 = (const float*)d_in[9];
    const float* ar2 = (const float*)d_in[10];
    const float* b2  = (const float*)d_in[11];
    float* out = (float*)d_out;
    (void)in_sizes; (void)n_in; (void)out_size;

    void *p_feat1 = nullptr, *p_out1 = nullptr, *p_feat2 = nullptr;
    void *p_W2p = nullptr, *p_al2p = nullptr, *p_ar2p = nullptr;
    void *p_counts = nullptr, *p_elr = nullptr;
    cudaGetSymbolAddress(&p_feat1, g_feat1h);
    cudaGetSymbolAddress(&p_out1,  g_out1h);
    cudaGetSymbolAddress(&p_feat2, g_feat2h);
    cudaGetSymbolAddress(&p_W2p,   g_W2p);
    cudaGetSymbolAddress(&p_al2p,  g_al2p);
    cudaGetSymbolAddress(&p_ar2p,  g_ar2p);
    cudaGetSymbolAddress(&p_counts, g_counts);
    cudaGetSymbolAddress(&p_elr,   g_elr);

    const int NP1v = N_NODES + 1;
    const int SCAN_BLOCKS = (NP1v + 1023) / 1024;
    const int EB = (N_EDGES + 255) / 256;
    const int NODE_WARP_BLOCKS = (N_NODES + 7) / 8;
    const int GB = (N_NODES + 127) / 128;

    size_t gsm1 = (size_t)(128 * LDA + 2 * 128 * LDB) * sizeof(__half);  // NP=2
    size_t gsm2 = (size_t)(128 * LDA + 1 * 128 * LDB) * sizeof(__half);  // NP=1
    cudaFuncSetAttribute((const void*)gemm_tc_k<false, false, true, false, 2>,
                         cudaFuncAttributeMaxDynamicSharedMemorySize, (int)gsm1);
    cudaFuncSetAttribute((const void*)gemm_tc_k<true, true, false, true, 1>,
                         cudaFuncAttributeMaxDynamicSharedMemorySize, (int)gsm2);

    cudaStream_t s1;
    cudaStreamCreateWithFlags(&s1, cudaStreamNonBlocking);
    cudaEvent_t evFork, evJoin;
    cudaEventCreateWithFlags(&evFork, cudaEventDisableTiming);
    cudaEventCreateWithFlags(&evJoin, cudaEventDisableTiming);

    // fork: branch B (s1) = pad2 + GEMM1(+eler1); branch A (default) = CSR chain
    cudaEventRecord(evFork, 0);
    cudaStreamWaitEvent(s1, evFork, 0);

    // branch B on s1
    pad2_k<<<(KIN * HD2P + 255) / 256, 256, 0, s1>>>(W2, b2, al2, ar2);
    dim3 g1(GB, 1);
    gemm_tc_k<false, false, true, false, 2><<<g1, 256, gsm1, s1>>>(
        x, W1, (__half*)p_feat1, nullptr, al1, ar1, N_NODES, HD1);

    // branch A on default stream: CSR build
    cudaMemsetAsync(p_counts, 0, (size_t)NP1v * sizeof(int), 0);
    hist_k<<<EB, 256>>>(dst);
    scan_block_k<<<SCAN_BLOCKS, 1024>>>(NP1v);
    scan_add_k<<<SCAN_BLOCKS, 1024>>>(NP1v);
    scatter_k<<<EB, 256>>>(src, dst);

    // join: attn_agg1 needs CSR (A) + feat1h/el/er (B)
    cudaEventRecord(evJoin, s1);
    cudaStreamWaitEvent(0, evJoin, 0);

    // ---- Layer 1 ----
    attn_agg1_k<<<NODE_WARP_BLOCKS, 256>>>(b1);

    // ---- Layer 2: zero el/er, then GEMM2 with fused eler epilogue ----
    cudaMemsetAsync(p_elr, 0, (size_t)2 * N_NODES * 4 * sizeof(float), 0);
    dim3 g2(GB, 3);
    gemm_tc_k<true, true, false, true, 1><<<g2, 256, gsm2>>>(
        p_out1, (const float*)p_W2p, (__half*)p_feat2, inv,
        (const float*)p_al2p, (const float*)p_ar2p, N_NODES, HD2P);
    attn_agg2_k<<<NODE_WARP_BLOCKS, 256>>>(out);

    cudaEventDestroy(evFork);
    cudaEventDestroy(evJoin);
    cudaStreamDestroy(s1);
}